// round 12
// baseline (speedup 1.0000x reference)
#include <cuda_runtime.h>
#include <cuda_bf16.h>
#include <math.h>
#include <stdint.h>

#define BB 2
#define TT 2048
#define DD 1024
#define HH 16
#define DH 64
#define MM (BB*TT)

/* ---- gemm geometry: CTA 128x128, 8 warps (64x32), k-chunk 64, 3-stage ---- */
#define GST 72
#define GTILE (128*GST)
#define GSTAGE (4*GTILE)
#define NSTG 3
#define NCH  16
#define GEMM_SMEM (NSTG*GSTAGE*2)   /* 221184 B */
#define FST 132                     /* fp32 staging stride (floats) */

#define KST 72
#define ATILE (64*KST)
#define STAGE (6*ATILE)

// ---------------- scratch (device globals) ----------------------------------
__device__ float2 g_cs[TT*32];
__device__ __nv_bfloat16 g_xh [MM*DD], g_xl [MM*DD];
__device__ __nv_bfloat16 g_zh [MM*DD], g_zl [MM*DD];
__device__ __nv_bfloat16 g_w6h[6*DD*DD], g_w6l[6*DD*DD];
__device__ __nv_bfloat16 g_qh [MM*DD], g_ql [MM*DD];
__device__ __nv_bfloat16 g_q2h[MM*DD], g_q2l[MM*DD];
__device__ __nv_bfloat16 g_kh [MM*DD], g_kl [MM*DD];
__device__ __nv_bfloat16 g_k2h[MM*DD], g_k2l[MM*DD];
__device__ __nv_bfloat16 g_vh [MM*DD], g_vl [MM*DD];

struct Outs { __nv_bfloat16* hi[5]; __nv_bfloat16* lo[5]; };

// ---------------------------------------------------------------------------
__device__ __forceinline__ uint32_t saddr(const void* p) {
    return (uint32_t)__cvta_generic_to_shared(p);
}
__device__ __forceinline__ void ldmat_x4(uint32_t (&r)[4], uint32_t a) {
    asm volatile("ldmatrix.sync.aligned.m8n8.x4.shared.b16 {%0,%1,%2,%3}, [%4];"
                 : "=r"(r[0]), "=r"(r[1]), "=r"(r[2]), "=r"(r[3]) : "r"(a));
}
__device__ __forceinline__ void ldmat_x4_trans(uint32_t (&r)[4], uint32_t a) {
    asm volatile("ldmatrix.sync.aligned.m8n8.x4.trans.shared.b16 {%0,%1,%2,%3}, [%4];"
                 : "=r"(r[0]), "=r"(r[1]), "=r"(r[2]), "=r"(r[3]) : "r"(a));
}
__device__ __forceinline__ void mma16816(float (&d)[4], const uint32_t (&a)[4],
                                         uint32_t b0, uint32_t b1) {
    asm volatile(
        "mma.sync.aligned.m16n8k16.row.col.f32.bf16.bf16.f32 "
        "{%0,%1,%2,%3}, {%4,%5,%6,%7}, {%8,%9}, {%0,%1,%2,%3};"
        : "+f"(d[0]), "+f"(d[1]), "+f"(d[2]), "+f"(d[3])
        : "r"(a[0]), "r"(a[1]), "r"(a[2]), "r"(a[3]), "r"(b0), "r"(b1));
}
__device__ __forceinline__ void cpa16(void* dst, const void* src) {
    asm volatile("cp.async.cg.shared.global [%0], [%1], 16;"
                 :: "r"(saddr(dst)), "l"(src));
}
__device__ __forceinline__ void cpa_commit() { asm volatile("cp.async.commit_group;"); }
__device__ __forceinline__ void cpa_wait0()  { asm volatile("cp.async.wait_group 0;"); }
__device__ __forceinline__ void cpa_wait1()  { asm volatile("cp.async.wait_group 1;"); }

__device__ __forceinline__ void fsplit(float x, unsigned short& h, unsigned short& l) {
    __nv_bfloat16 hb = __float2bfloat16_rn(x);
    __nv_bfloat16 lb = __float2bfloat16_rn(x - __bfloat162float(hb));
    h = __bfloat16_as_ushort(hb);
    l = __bfloat16_as_ushort(lb);
}

// ---------------------------------------------------------------------------
// cos/sin table (bit-identical expressions to the old rope_split)
// ---------------------------------------------------------------------------
__global__ void build_cs(float2* cs) {
    const int idx = blockIdx.x * 256 + threadIdx.x;   // < 65536
    const int t = idx >> 5;
    const int i = idx & 31;
    const float inv_freq = powf(10000.0f, -(float)i * (1.0f / 32.0f));
    float c, s;
    sincosf((float)t * inv_freq, &s, &c);
    cs[idx] = make_float2(c, s);
}

// ---------------------------------------------------------------------------
// splits
// ---------------------------------------------------------------------------
__global__ void split_f32(const float* __restrict__ in,
                          __nv_bfloat16* __restrict__ hi,
                          __nv_bfloat16* __restrict__ lo) {
    const size_t i = ((size_t)blockIdx.x * 256 + threadIdx.x) * 4;
    float4 v = *(const float4*)(in + i);
    float f[4] = {v.x, v.y, v.z, v.w};
    unsigned short h[4], l[4];
#pragma unroll
    for (int e = 0; e < 4; e++) fsplit(f[e], h[e], l[e]);
    *(uint2*)(hi + i) = make_uint2((uint32_t)h[1] << 16 | h[0],
                                   (uint32_t)h[3] << 16 | h[2]);
    *(uint2*)(lo + i) = make_uint2((uint32_t)l[1] << 16 | l[0],
                                   (uint32_t)l[3] << 16 | l[2]);
}

__global__ void split_w6(const float* __restrict__ w0, const float* __restrict__ w1,
                         const float* __restrict__ w2, const float* __restrict__ w3,
                         const float* __restrict__ w4, const float* __restrict__ w5,
                         __nv_bfloat16* __restrict__ hi, __nv_bfloat16* __restrict__ lo) {
    const float* src[6] = {w0, w1, w2, w3, w4, w5};
    const float* in = src[blockIdx.y];
    const size_t off = (size_t)blockIdx.y * DD * DD;
    const size_t i = ((size_t)blockIdx.x * 256 + threadIdx.x) * 4;
    float4 v = *(const float4*)(in + i);
    float f[4] = {v.x, v.y, v.z, v.w};
    unsigned short h[4], l[4];
#pragma unroll
    for (int e = 0; e < 4; e++) fsplit(f[e], h[e], l[e]);
    *(uint2*)(hi + off + i) = make_uint2((uint32_t)h[1] << 16 | h[0],
                                         (uint32_t)h[3] << 16 | h[2]);
    *(uint2*)(lo + off + i) = make_uint2((uint32_t)l[1] << 16 | l[0],
                                         (uint32_t)l[3] << 16 | l[2]);
}

// ---------------------------------------------------------------------------
// C[M,N] = A[M,K] @ W[N,K]^T, bf16 hi/lo 3-term mma.sync (round-10 mainloop).
// Cf32 != null : plain fp32 epilogue (out-projection).
// Cf32 == null : fp32-smem-staged RoPE + hi/lo split epilogue.
//                zi<4: RoPE; zi==4 (v): identity passthrough.
// ---------------------------------------------------------------------------
__global__ void __launch_bounds__(256, 1) gemm_bf16(
        const __nv_bfloat16* __restrict__ Ah, const __nv_bfloat16* __restrict__ Al,
        const __nv_bfloat16* __restrict__ Wh, const __nv_bfloat16* __restrict__ Wl,
        float* __restrict__ Cf32, Outs outs, const float2* __restrict__ cs) {
    extern __shared__ __nv_bfloat16 sg[];
    const int zi = blockIdx.z;
    Wh += (size_t)zi * DD * DD;
    Wl += (size_t)zi * DD * DD;

    const int tid  = threadIdx.x;
    const int wid  = tid >> 5;
    const int lane = tid & 31;
    const int m0 = blockIdx.y * 128;
    const int n0 = blockIdx.x * 128;
    const int wm = wid & 1;
    const int wn = wid >> 1;

    auto load_chunk = [&](int c) {
        __nv_bfloat16* base = sg + (c % NSTG) * GSTAGE;
        const int k0 = c * 64;
#pragma unroll 4
        for (int i = tid; i < 1024; i += 256) {
            const int r  = i >> 3;
            const int ck = (i & 7) * 8;
            const int so = r * GST + ck;
            cpa16(base + 0 * GTILE + so, Ah + (size_t)(m0 + r) * DD + k0 + ck);
            cpa16(base + 1 * GTILE + so, Al + (size_t)(m0 + r) * DD + k0 + ck);
            cpa16(base + 2 * GTILE + so, Wh + (size_t)(n0 + r) * DD + k0 + ck);
            cpa16(base + 3 * GTILE + so, Wl + (size_t)(n0 + r) * DD + k0 + ck);
        }
        cpa_commit();
    };

    float acc[4][4][4];
#pragma unroll
    for (int i = 0; i < 4; i++)
#pragma unroll
        for (int j = 0; j < 4; j++)
#pragma unroll
            for (int c = 0; c < 4; c++) acc[i][j][c] = 0.0f;

    load_chunk(0);
    load_chunk(1);

    for (int ch = 0; ch < NCH; ch++) {
        if (ch + 1 < NCH) cpa_wait1();
        else              cpa_wait0();
        __syncthreads();
        if (ch + 2 < NCH) load_chunk(ch + 2);

        const __nv_bfloat16* cur = sg + (ch % NSTG) * GSTAGE;
        const __nv_bfloat16* Ahi = cur;
        const __nv_bfloat16* Alo = cur + GTILE;
        const __nv_bfloat16* Bhi = cur + 2 * GTILE;
        const __nv_bfloat16* Blo = cur + 3 * GTILE;

#pragma unroll
        for (int kk = 0; kk < 4; kk++) {
            uint32_t ahi[4][4], alo[4][4], bhi[2][4], blo[2][4];
            const int ar = wm * 64 + (lane & 15);
            const int ak = kk * 16 + (lane >> 4) * 8;
#pragma unroll
            for (int mi = 0; mi < 4; mi++) {
                ldmat_x4(ahi[mi], saddr(Ahi + (ar + mi * 16) * GST + ak));
                ldmat_x4(alo[mi], saddr(Alo + (ar + mi * 16) * GST + ak));
            }
            const int br = wn * 32 + ((lane >> 4) & 1) * 8 + (lane & 7);
            const int bk = kk * 16 + ((lane >> 3) & 1) * 8;
#pragma unroll
            for (int p = 0; p < 2; p++) {
                ldmat_x4(bhi[p], saddr(Bhi + (br + p * 16) * GST + bk));
                ldmat_x4(blo[p], saddr(Blo + (br + p * 16) * GST + bk));
            }
#pragma unroll
            for (int mi = 0; mi < 4; mi++)
#pragma unroll
                for (int ni = 0; ni < 4; ni++) {
                    const uint32_t* bh = &bhi[ni >> 1][(ni & 1) * 2];
                    mma16816(acc[mi][ni], ahi[mi], bh[0], bh[1]);
                }
#pragma unroll
            for (int mi = 0; mi < 4; mi++)
#pragma unroll
                for (int ni = 0; ni < 4; ni++) {
                    const uint32_t* bl = &blo[ni >> 1][(ni & 1) * 2];
                    mma16816(acc[mi][ni], ahi[mi], bl[0], bl[1]);
                }
#pragma unroll
            for (int mi = 0; mi < 4; mi++)
#pragma unroll
                for (int ni = 0; ni < 4; ni++) {
                    const uint32_t* bh = &bhi[ni >> 1][(ni & 1) * 2];
                    mma16816(acc[mi][ni], alo[mi], bh[0], bh[1]);
                }
        }
    }

    if (Cf32 != nullptr) {
        // plain fp32 epilogue (out-projection) — identical to round 10
        float* C = Cf32;
#pragma unroll
        for (int mi = 0; mi < 4; mi++)
#pragma unroll
            for (int ni = 0; ni < 4; ni++) {
                const int r0 = m0 + wm * 64 + mi * 16 + (lane >> 2);
                const int c0 = n0 + wn * 32 + ni * 8 + (lane & 3) * 2;
                *(float2*)(C + (size_t)r0 * 1024 + c0) =
                    make_float2(acc[mi][ni][0], acc[mi][ni][1]);
                *(float2*)(C + (size_t)(r0 + 8) * 1024 + c0) =
                    make_float2(acc[mi][ni][2], acc[mi][ni][3]);
            }
        return;
    }

    // -------- fp32-staged rope/split epilogue (no weight permutation) --------
    float* Sf = (float*)sg;                 // 128 x FST fp32 = 67584 B
    __syncthreads();                        // mainloop smem reads done

#pragma unroll
    for (int mi = 0; mi < 4; mi++)
#pragma unroll
        for (int ni = 0; ni < 4; ni++) {
            const int rl = wm * 64 + mi * 16 + (lane >> 2);
            const int c0 = wn * 32 + ni * 8 + (lane & 3) * 2;
            *(float2*)(Sf + rl * FST + c0) =
                make_float2(acc[mi][ni][0], acc[mi][ni][1]);
            *(float2*)(Sf + (rl + 8) * FST + c0) =
                make_float2(acc[mi][ni][2], acc[mi][ni][3]);
        }
    __syncthreads();

    __nv_bfloat16* Oh = outs.hi[zi];
    __nv_bfloat16* Ol = outs.lo[zi];
    const bool dorope = (zi != 4);
    for (int it = tid; it < 16384; it += 256) {
        const int r = it >> 7;          // 0..127
        const int c = it & 127;         // 0..127 (warp-uniform 32-col span)
        float y;
        if (dorope) {
            const int t = (m0 + r) & (TT - 1);
            const float2 c2 = cs[t * 32 + (c & 31)];
            if ((c & 63) < 32) {
                const float x1 = Sf[r * FST + c];
                const float x2 = Sf[r * FST + c + 32];
                y = fmaf(x1, c2.x, x2 * c2.y);
            } else {
                const float x1 = Sf[r * FST + c - 32];
                const float x2 = Sf[r * FST + c];
                y = fmaf(-x1, c2.y, x2 * c2.x);
            }
        } else {
            y = Sf[r * FST + c];
        }
        unsigned short hh, ll;
        fsplit(y, hh, ll);
        const size_t go = (size_t)(m0 + r) * DD + n0 + c;
        Oh[go] = __ushort_as_bfloat16(hh);
        Ol[go] = __ushort_as_bfloat16(ll);
    }
}

// ---------------------------------------------------------------------------
// Tensor-core causal bilinear attention (unchanged from round 10).
// ---------------------------------------------------------------------------
__global__ void __launch_bounds__(256, 1) attn_mma(
        const __nv_bfloat16* __restrict__ qh,  const __nv_bfloat16* __restrict__ ql,
        const __nv_bfloat16* __restrict__ q2h, const __nv_bfloat16* __restrict__ q2l,
        const __nv_bfloat16* __restrict__ kh,  const __nv_bfloat16* __restrict__ kl,
        const __nv_bfloat16* __restrict__ k2h, const __nv_bfloat16* __restrict__ k2l,
        const __nv_bfloat16* __restrict__ vh,  const __nv_bfloat16* __restrict__ vl,
        __nv_bfloat16* __restrict__ zh, __nv_bfloat16* __restrict__ zl) {
    extern __shared__ __nv_bfloat16 sb2[];
    const int tid  = threadIdx.x;
    const int lane = tid & 31;
    const int w    = tid >> 5;
    const int qb = (int)gridDim.x - 1 - (int)blockIdx.x;
    const int q0 = qb * 128;
    const int b  = blockIdx.y >> 4;
    const int h  = blockIdx.y & 15;
    const size_t bh_off = (size_t)b * TT * DD + h * DH;

    {
        const __nv_bfloat16* src[4] = {qh, ql, q2h, q2l};
#pragma unroll
        for (int a = 0; a < 4; a++) {
            __nv_bfloat16* dst = sb2 + a * 128 * KST;
            for (int i = tid; i < 1024; i += 256) {
                const int r = i >> 3, ck = (i & 7) * 8;
                cpa16(dst + r * KST + ck, src[a] + bh_off + (size_t)(q0 + r) * DD + ck);
            }
        }
        cpa_commit();
        cpa_wait0();
        __syncthreads();
    }

    uint32_t fqh[4][4], fql[4][4], fq2h[4][4], fq2l[4][4];
    {
        const int ar = w * 16 + (lane & 15);
        const int ak = (lane >> 4) * 8;
#pragma unroll
        for (int kf = 0; kf < 4; kf++) {
            ldmat_x4(fqh [kf], saddr(sb2 + 0 * 128 * KST + ar * KST + kf * 16 + ak));
            ldmat_x4(fql [kf], saddr(sb2 + 1 * 128 * KST + ar * KST + kf * 16 + ak));
            ldmat_x4(fq2h[kf], saddr(sb2 + 2 * 128 * KST + ar * KST + kf * 16 + ak));
            ldmat_x4(fq2l[kf], saddr(sb2 + 3 * 128 * KST + ar * KST + kf * 16 + ak));
        }
    }
    __syncthreads();

    float zacc[8][4];
#pragma unroll
    for (int i = 0; i < 8; i++)
#pragma unroll
        for (int j = 0; j < 4; j++) zacc[i][j] = 0.0f;

    const int nkv = 2 * qb + 2;
    const int br = (lane & 7) + ((lane >> 4) & 1) * 8;
    const int bk = ((lane >> 3) & 1) * 8;
    const float invd2 = 1.0f / ((float)DH * (float)DH);

    auto load_tile = [&](int kj, int buf) {
        __nv_bfloat16* base = sb2 + buf * STAGE;
        const int kv0 = kj * 64;
        const __nv_bfloat16* src[6] = {kh, kl, k2h, k2l, vh, vl};
#pragma unroll
        for (int a = 0; a < 6; a++) {
            __nv_bfloat16* dst = base + a * ATILE;
            for (int i = tid; i < 512; i += 256) {
                const int r = i >> 3, ck = (i & 7) * 8;
                cpa16(dst + r * KST + ck, src[a] + bh_off + (size_t)(kv0 + r) * DD + ck);
            }
        }
    };

    load_tile(0, 0);
    cpa_commit();

    for (int kj = 0; kj < nkv; kj++) {
        cpa_wait0();
        __syncthreads();
        if (kj + 1 < nkv) {
            load_tile(kj + 1, (kj + 1) & 1);
            cpa_commit();
        }

        const __nv_bfloat16* base = sb2 + (kj & 1) * STAGE;
        const int kv0 = kj * 64;
        const bool masked = (kv0 >= q0);

        uint32_t ph[8][2], pl[8][2];
#pragma unroll
        for (int g = 0; g < 4; g++) {
            float s1f[2][4], s2f[2][4];
#pragma unroll
            for (int p = 0; p < 2; p++)
#pragma unroll
                for (int e = 0; e < 4; e++) { s1f[p][e] = 0.0f; s2f[p][e] = 0.0f; }

#pragma unroll
            for (int kf = 0; kf < 4; kf++) {
                uint32_t kh_[4], kl_[4], k2h_[4], k2l_[4];
                const int off = (g * 16 + br) * KST + kf * 16 + bk;
                ldmat_x4(kh_,  saddr(base + 0 * ATILE + off));
                ldmat_x4(kl_,  saddr(base + 1 * ATILE + off));
                ldmat_x4(k2h_, saddr(base + 2 * ATILE + off));
                ldmat_x4(k2l_, saddr(base + 3 * ATILE + off));
#pragma unroll
                for (int p = 0; p < 2; p++) {
                    mma16816(s1f[p], fqh[kf],  kh_[p*2],  kh_[p*2+1]);
                    mma16816(s2f[p], fq2h[kf], k2h_[p*2], k2h_[p*2+1]);
                }
#pragma unroll
                for (int p = 0; p < 2; p++) {
                    mma16816(s1f[p], fqh[kf],  kl_[p*2],  kl_[p*2+1]);
                    mma16816(s2f[p], fq2h[kf], k2l_[p*2], k2l_[p*2+1]);
                }
#pragma unroll
                for (int p = 0; p < 2; p++) {
                    mma16816(s1f[p], fql[kf],  kh_[p*2],  kh_[p*2+1]);
                    mma16816(s2f[p], fq2l[kf], k2h_[p*2], k2h_[p*2+1]);
                }
            }
#pragma unroll
            for (int p = 0; p < 2; p++) {
                const int j = g * 2 + p;
                float pr[4];
#pragma unroll
                for (int e = 0; e < 4; e++) pr[e] = s1f[p][e] * s2f[p][e] * invd2;
                if (masked) {
                    const int qr = q0 + w * 16 + (lane >> 2);
                    const int kc = kv0 + j * 8 + (lane & 3) * 2;
                    if (kc     > qr)     pr[0] = 0.0f;
                    if (kc + 1 > qr)     pr[1] = 0.0f;
                    if (kc     > qr + 8) pr[2] = 0.0f;
                    if (kc + 1 > qr + 8) pr[3] = 0.0f;
                }
                unsigned short hh[4], ll[4];
#pragma unroll
                for (int e = 0; e < 4; e++) fsplit(pr[e], hh[e], ll[e]);
                ph[j][0] = (uint32_t)hh[1] << 16 | hh[0];
                ph[j][1] = (uint32_t)hh[3] << 16 | hh[2];
                pl[j][0] = (uint32_t)ll[1] << 16 | ll[0];
                pl[j][1] = (uint32_t)ll[3] << 16 | ll[2];
            }
        }

        const int vr_lane = ((lane >> 3) & 1) * 8 + (lane & 7);
        const int vc_lane = ((lane >> 4) & 1) * 8;
#pragma unroll
        for (int f = 0; f < 4; f++) {
            uint32_t ah[4] = {ph[2*f][0], ph[2*f][1], ph[2*f+1][0], ph[2*f+1][1]};
            uint32_t al[4] = {pl[2*f][0], pl[2*f][1], pl[2*f+1][0], pl[2*f+1][1]};
            uint32_t vh_[4][4], vl_[4][4];
#pragma unroll
            for (int gd = 0; gd < 4; gd++) {
                const int off = (f * 16 + vr_lane) * KST + gd * 16 + vc_lane;
                ldmat_x4_trans(vh_[gd], saddr(base + 4 * ATILE + off));
                ldmat_x4_trans(vl_[gd], saddr(base + 5 * ATILE + off));
            }
#pragma unroll
            for (int gd = 0; gd < 4; gd++)
#pragma unroll
                for (int p = 0; p < 2; p++)
                    mma16816(zacc[gd*2+p], ah, vh_[gd][p*2], vh_[gd][p*2+1]);
#pragma unroll
            for (int gd = 0; gd < 4; gd++)
#pragma unroll
                for (int p = 0; p < 2; p++)
                    mma16816(zacc[gd*2+p], ah, vl_[gd][p*2], vl_[gd][p*2+1]);
#pragma unroll
            for (int gd = 0; gd < 4; gd++)
#pragma unroll
                for (int p = 0; p < 2; p++)
                    mma16816(zacc[gd*2+p], al, vh_[gd][p*2], vh_[gd][p*2+1]);
        }
    }

    {
        const int r = q0 + w * 16 + (lane >> 2);
        const int c = (lane & 3) * 2;
#pragma unroll
        for (int nd = 0; nd < 8; nd++) {
            unsigned short h0, l0, h1, l1;
#pragma unroll
            for (int half = 0; half < 2; half++) {
                fsplit(zacc[nd][half * 2 + 0], h0, l0);
                fsplit(zacc[nd][half * 2 + 1], h1, l1);
                const size_t off = bh_off + (size_t)(r + half * 8) * DD + nd * 8 + c;
                *(uint32_t*)(zh + off) = (uint32_t)h1 << 16 | h0;
                *(uint32_t*)(zl + off) = (uint32_t)l1 << 16 | l0;
            }
        }
    }
}

// ---------------------------------------------------------------------------
extern "C" void kernel_launch(void* const* d_in, const int* in_sizes, int n_in,
                              void* d_out, int out_size) {
    const float* x     = (const float*)d_in[0];
    const float* Wq    = (const float*)d_in[1];
    const float* Wk    = (const float*)d_in[2];
    const float* Wq2   = (const float*)d_in[3];
    const float* Wk2   = (const float*)d_in[4];
    const float* Wv    = (const float*)d_in[5];
    const float* Wproj = (const float*)d_in[6];
    float* out = (float*)d_out;

    float2* cs;
    cudaGetSymbolAddress((void**)&cs, g_cs);

    __nv_bfloat16 *xh, *xl, *zh, *zl, *w6h, *w6l;
    cudaGetSymbolAddress((void**)&xh,  g_xh);  cudaGetSymbolAddress((void**)&xl,  g_xl);
    cudaGetSymbolAddress((void**)&zh,  g_zh);  cudaGetSymbolAddress((void**)&zl,  g_zl);
    cudaGetSymbolAddress((void**)&w6h, g_w6h); cudaGetSymbolAddress((void**)&w6l, g_w6l);

    __nv_bfloat16 *qh, *ql, *q2h, *q2l, *kh, *kl, *k2h, *k2l, *vh, *vl;
    cudaGetSymbolAddress((void**)&qh,  g_qh);  cudaGetSymbolAddress((void**)&ql,  g_ql);
    cudaGetSymbolAddress((void**)&q2h, g_q2h); cudaGetSymbolAddress((void**)&q2l, g_q2l);
    cudaGetSymbolAddress((void**)&kh,  g_kh);  cudaGetSymbolAddress((void**)&kl,  g_kl);
    cudaGetSymbolAddress((void**)&k2h, g_k2h); cudaGetSymbolAddress((void**)&k2l, g_k2l);
    cudaGetSymbolAddress((void**)&vh,  g_vh);  cudaGetSymbolAddress((void**)&vl,  g_vl);

    Outs outs;
    outs.hi[0] = qh;  outs.lo[0] = ql;
    outs.hi[1] = kh;  outs.lo[1] = kl;
    outs.hi[2] = q2h; outs.lo[2] = q2l;
    outs.hi[3] = k2h; outs.lo[3] = k2l;
    outs.hi[4] = vh;  outs.lo[4] = vl;

    cudaFuncSetAttribute(gemm_bf16,
                         cudaFuncAttributeMaxDynamicSharedMemorySize, GEMM_SMEM);

    // 0) cos/sin table
    build_cs<<<TT * 32 / 256, 256>>>(cs);

    // 1) split inputs
    split_f32<<<MM * DD / 1024, 256>>>(x, xh, xl);
    split_w6<<<dim3(DD * DD / 1024, 6), 256>>>(Wq, Wk, Wq2, Wk2, Wv, Wproj, w6h, w6l);

    // 2) five fused projections with staged RoPE + split epilogue
    gemm_bf16<<<dim3(DD / 128, MM / 128, 5), 256, GEMM_SMEM>>>(
        xh, xl, w6h, w6l, nullptr, outs, cs);

    // 3) attention (writes zh/zl directly)
    const int attn_smem = 2 * STAGE * (int)sizeof(__nv_bfloat16);
    cudaFuncSetAttribute(attn_mma,
                         cudaFuncAttributeMaxDynamicSharedMemorySize, attn_smem);
    attn_mma<<<dim3(TT / 128, BB * HH), 256, attn_smem>>>(
        qh, ql, q2h, q2l, kh, kl, k2h, k2l, vh, vl, zh, zl);

    // 4) output projection (plain fp32 epilogue)
    gemm_bf16<<<dim3(DD / 128, MM / 128, 1), 256, GEMM_SMEM>>>(
        zh, zl, w6h + (size_t)5 * DD * DD, w6l + (size_t)5 * DD * DD, out, outs, cs);
}

// round 13
// speedup vs baseline: 1.1153x; 1.1153x over previous
#include <cuda_runtime.h>
#include <cuda_bf16.h>
#include <math.h>
#include <stdint.h>

#define BB 2
#define TT 2048
#define DD 1024
#define HH 16
#define DH 64
#define MM (BB*TT)

/* ---- gemm geometry: CTA 128x128, 8 warps (64x32), k-chunk 64, 3-stage ---- */
#define GST 72
#define GTILE (128*GST)
#define GSTAGE (4*GTILE)
#define NSTG 3
#define NCH  16
#define GEMM_SMEM (NSTG*GSTAGE*2)   /* 221184 B */
#define FST 132                     /* fp32 staging stride (floats) */

#define KST 72
#define ATILE (64*KST)
#define STAGE (6*ATILE)

// ---------------- scratch (device globals) ----------------------------------
__device__ float2 g_cs[TT*32];
__device__ __nv_bfloat16 g_xh [MM*DD], g_xl [MM*DD];
__device__ __nv_bfloat16 g_zh [MM*DD], g_zl [MM*DD];
__device__ __nv_bfloat16 g_w6h[6*DD*DD], g_w6l[6*DD*DD];
__device__ __nv_bfloat16 g_qh [MM*DD], g_ql [MM*DD];
__device__ __nv_bfloat16 g_q2h[MM*DD], g_q2l[MM*DD];
__device__ __nv_bfloat16 g_kh [MM*DD], g_kl [MM*DD];
__device__ __nv_bfloat16 g_k2h[MM*DD], g_k2l[MM*DD];
__device__ __nv_bfloat16 g_vh [MM*DD], g_vl [MM*DD];

struct Outs { __nv_bfloat16* hi[5]; __nv_bfloat16* lo[5]; };

// ---------------------------------------------------------------------------
__device__ __forceinline__ uint32_t saddr(const void* p) {
    return (uint32_t)__cvta_generic_to_shared(p);
}
__device__ __forceinline__ void ldmat_x4(uint32_t (&r)[4], uint32_t a) {
    asm volatile("ldmatrix.sync.aligned.m8n8.x4.shared.b16 {%0,%1,%2,%3}, [%4];"
                 : "=r"(r[0]), "=r"(r[1]), "=r"(r[2]), "=r"(r[3]) : "r"(a));
}
__device__ __forceinline__ void ldmat_x4_trans(uint32_t (&r)[4], uint32_t a) {
    asm volatile("ldmatrix.sync.aligned.m8n8.x4.trans.shared.b16 {%0,%1,%2,%3}, [%4];"
                 : "=r"(r[0]), "=r"(r[1]), "=r"(r[2]), "=r"(r[3]) : "r"(a));
}
__device__ __forceinline__ void mma16816(float (&d)[4], const uint32_t (&a)[4],
                                         uint32_t b0, uint32_t b1) {
    asm volatile(
        "mma.sync.aligned.m16n8k16.row.col.f32.bf16.bf16.f32 "
        "{%0,%1,%2,%3}, {%4,%5,%6,%7}, {%8,%9}, {%0,%1,%2,%3};"
        : "+f"(d[0]), "+f"(d[1]), "+f"(d[2]), "+f"(d[3])
        : "r"(a[0]), "r"(a[1]), "r"(a[2]), "r"(a[3]), "r"(b0), "r"(b1));
}
__device__ __forceinline__ void cpa16(void* dst, const void* src) {
    asm volatile("cp.async.cg.shared.global [%0], [%1], 16;"
                 :: "r"(saddr(dst)), "l"(src));
}
__device__ __forceinline__ void cpa_commit() { asm volatile("cp.async.commit_group;"); }
__device__ __forceinline__ void cpa_wait0()  { asm volatile("cp.async.wait_group 0;"); }
__device__ __forceinline__ void cpa_wait1()  { asm volatile("cp.async.wait_group 1;"); }

__device__ __forceinline__ void fsplit(float x, unsigned short& h, unsigned short& l) {
    __nv_bfloat16 hb = __float2bfloat16_rn(x);
    __nv_bfloat16 lb = __float2bfloat16_rn(x - __bfloat162float(hb));
    h = __bfloat16_as_ushort(hb);
    l = __bfloat16_as_ushort(lb);
}

// ---------------------------------------------------------------------------
// cos/sin table (bit-identical expressions to the original rope)
// ---------------------------------------------------------------------------
__global__ void build_cs(float2* cs) {
    const int idx = blockIdx.x * 256 + threadIdx.x;
    const int t = idx >> 5;
    const int i = idx & 31;
    const float inv_freq = powf(10000.0f, -(float)i * (1.0f / 32.0f));
    float c, s;
    sincosf((float)t * inv_freq, &s, &c);
    cs[idx] = make_float2(c, s);
}

// ---------------------------------------------------------------------------
// splits
// ---------------------------------------------------------------------------
__global__ void split_f32(const float* __restrict__ in,
                          __nv_bfloat16* __restrict__ hi,
                          __nv_bfloat16* __restrict__ lo) {
    const size_t i = ((size_t)blockIdx.x * 256 + threadIdx.x) * 4;
    float4 v = *(const float4*)(in + i);
    float f[4] = {v.x, v.y, v.z, v.w};
    unsigned short h[4], l[4];
#pragma unroll
    for (int e = 0; e < 4; e++) fsplit(f[e], h[e], l[e]);
    *(uint2*)(hi + i) = make_uint2((uint32_t)h[1] << 16 | h[0],
                                   (uint32_t)h[3] << 16 | h[2]);
    *(uint2*)(lo + i) = make_uint2((uint32_t)l[1] << 16 | l[0],
                                   (uint32_t)l[3] << 16 | l[2]);
}

__global__ void split_w6(const float* __restrict__ w0, const float* __restrict__ w1,
                         const float* __restrict__ w2, const float* __restrict__ w3,
                         const float* __restrict__ w4, const float* __restrict__ w5,
                         __nv_bfloat16* __restrict__ hi, __nv_bfloat16* __restrict__ lo) {
    const float* src[6] = {w0, w1, w2, w3, w4, w5};
    const float* in = src[blockIdx.y];
    const size_t off = (size_t)blockIdx.y * DD * DD;
    const size_t i = ((size_t)blockIdx.x * 256 + threadIdx.x) * 4;
    float4 v = *(const float4*)(in + i);
    float f[4] = {v.x, v.y, v.z, v.w};
    unsigned short h[4], l[4];
#pragma unroll
    for (int e = 0; e < 4; e++) fsplit(f[e], h[e], l[e]);
    *(uint2*)(hi + off + i) = make_uint2((uint32_t)h[1] << 16 | h[0],
                                         (uint32_t)h[3] << 16 | h[2]);
    *(uint2*)(lo + off + i) = make_uint2((uint32_t)l[1] << 16 | l[0],
                                         (uint32_t)l[3] << 16 | l[2]);
}

// ---------------------------------------------------------------------------
// shared mainloop (macro-free device function via #define to keep both
// kernels byte-equivalent in the hot path)
// ---------------------------------------------------------------------------
#define GEMM_MAINLOOP(Ah, Al, Wh, Wl, acc, sg, tid, m0, n0, wm, wn, lane)      \
    auto load_chunk = [&](int c) {                                             \
        __nv_bfloat16* base = sg + (c % NSTG) * GSTAGE;                        \
        const int k0 = c * 64;                                                 \
        _Pragma("unroll 4")                                                    \
        for (int i = tid; i < 1024; i += 256) {                                \
            const int r  = i >> 3;                                             \
            const int ck = (i & 7) * 8;                                        \
            const int so = r * GST + ck;                                       \
            cpa16(base + 0 * GTILE + so, Ah + (size_t)(m0 + r) * DD + k0 + ck);\
            cpa16(base + 1 * GTILE + so, Al + (size_t)(m0 + r) * DD + k0 + ck);\
            cpa16(base + 2 * GTILE + so, Wh + (size_t)(n0 + r) * DD + k0 + ck);\
            cpa16(base + 3 * GTILE + so, Wl + (size_t)(n0 + r) * DD + k0 + ck);\
        }                                                                      \
        cpa_commit();                                                          \
    };                                                                         \
    load_chunk(0);                                                             \
    load_chunk(1);                                                             \
    for (int ch = 0; ch < NCH; ch++) {                                         \
        if (ch + 1 < NCH) cpa_wait1();                                         \
        else              cpa_wait0();                                         \
        __syncthreads();                                                       \
        if (ch + 2 < NCH) load_chunk(ch + 2);                                  \
        const __nv_bfloat16* cur = sg + (ch % NSTG) * GSTAGE;                  \
        const __nv_bfloat16* Ahi = cur;                                        \
        const __nv_bfloat16* Alo = cur + GTILE;                                \
        const __nv_bfloat16* Bhi = cur + 2 * GTILE;                            \
        const __nv_bfloat16* Blo = cur + 3 * GTILE;                            \
        _Pragma("unroll")                                                      \
        for (int kk = 0; kk < 4; kk++) {                                       \
            uint32_t ahi[4][4], alo[4][4], bhi[2][4], blo[2][4];               \
            const int ar = wm * 64 + (lane & 15);                              \
            const int ak = kk * 16 + (lane >> 4) * 8;                          \
            _Pragma("unroll")                                                  \
            for (int mi = 0; mi < 4; mi++) {                                   \
                ldmat_x4(ahi[mi], saddr(Ahi + (ar + mi * 16) * GST + ak));     \
                ldmat_x4(alo[mi], saddr(Alo + (ar + mi * 16) * GST + ak));     \
            }                                                                  \
            const int br = wn * 32 + ((lane >> 4) & 1) * 8 + (lane & 7);       \
            const int bk = kk * 16 + ((lane >> 3) & 1) * 8;                    \
            _Pragma("unroll")                                                  \
            for (int p = 0; p < 2; p++) {                                      \
                ldmat_x4(bhi[p], saddr(Bhi + (br + p * 16) * GST + bk));       \
                ldmat_x4(blo[p], saddr(Blo + (br + p * 16) * GST + bk));       \
            }                                                                  \
            _Pragma("unroll")                                                  \
            for (int mi = 0; mi < 4; mi++)                                     \
                _Pragma("unroll")                                              \
                for (int ni = 0; ni < 4; ni++) {                               \
                    const uint32_t* bh = &bhi[ni >> 1][(ni & 1) * 2];          \
                    mma16816(acc[mi][ni], ahi[mi], bh[0], bh[1]);              \
                }                                                              \
            _Pragma("unroll")                                                  \
            for (int mi = 0; mi < 4; mi++)                                     \
                _Pragma("unroll")                                              \
                for (int ni = 0; ni < 4; ni++) {                               \
                    const uint32_t* bl = &blo[ni >> 1][(ni & 1) * 2];          \
                    mma16816(acc[mi][ni], ahi[mi], bl[0], bl[1]);              \
                }                                                              \
            _Pragma("unroll")                                                  \
            for (int mi = 0; mi < 4; mi++)                                     \
                _Pragma("unroll")                                              \
                for (int ni = 0; ni < 4; ni++) {                               \
                    const uint32_t* bh = &bhi[ni >> 1][(ni & 1) * 2];          \
                    mma16816(acc[mi][ni], alo[mi], bh[0], bh[1]);              \
                }                                                              \
        }                                                                      \
    }

// ---------------------------------------------------------------------------
// out-projection: plain fp32 epilogue (round-10 identical)
// ---------------------------------------------------------------------------
__global__ void __launch_bounds__(256, 1) gemm_plain(
        const __nv_bfloat16* __restrict__ Ah, const __nv_bfloat16* __restrict__ Al,
        const __nv_bfloat16* __restrict__ Wh, const __nv_bfloat16* __restrict__ Wl,
        float* __restrict__ C) {
    extern __shared__ __nv_bfloat16 sg[];
    const int tid  = threadIdx.x;
    const int wid  = tid >> 5;
    const int lane = tid & 31;
    const int m0 = blockIdx.y * 128;
    const int n0 = blockIdx.x * 128;
    const int wm = wid & 1;
    const int wn = wid >> 1;

    float acc[4][4][4];
#pragma unroll
    for (int i = 0; i < 4; i++)
#pragma unroll
        for (int j = 0; j < 4; j++)
#pragma unroll
            for (int c = 0; c < 4; c++) acc[i][j][c] = 0.0f;

    GEMM_MAINLOOP(Ah, Al, Wh, Wl, acc, sg, tid, m0, n0, wm, wn, lane)

#pragma unroll
    for (int mi = 0; mi < 4; mi++)
#pragma unroll
        for (int ni = 0; ni < 4; ni++) {
            const int r0 = m0 + wm * 64 + mi * 16 + (lane >> 2);
            const int c0 = n0 + wn * 32 + ni * 8 + (lane & 3) * 2;
            *(float2*)(C + (size_t)r0 * 1024 + c0) =
                make_float2(acc[mi][ni][0], acc[mi][ni][1]);
            *(float2*)(C + (size_t)(r0 + 8) * 1024 + c0) =
                make_float2(acc[mi][ni][2], acc[mi][ni][3]);
        }
}

// ---------------------------------------------------------------------------
// projections: fused vectorized RoPE + hi/lo split epilogue
// ---------------------------------------------------------------------------
__global__ void __launch_bounds__(256, 1) gemm_rope(
        const __nv_bfloat16* __restrict__ Ah, const __nv_bfloat16* __restrict__ Al,
        const __nv_bfloat16* __restrict__ Wh, const __nv_bfloat16* __restrict__ Wl,
        Outs outs, const float2* __restrict__ cs) {
    extern __shared__ __nv_bfloat16 sg[];
    const int zi = blockIdx.z;
    Wh += (size_t)zi * DD * DD;
    Wl += (size_t)zi * DD * DD;

    const int tid  = threadIdx.x;
    const int wid  = tid >> 5;
    const int lane = tid & 31;
    const int m0 = blockIdx.y * 128;
    const int n0 = blockIdx.x * 128;
    const int wm = wid & 1;
    const int wn = wid >> 1;

    float acc[4][4][4];
#pragma unroll
    for (int i = 0; i < 4; i++)
#pragma unroll
        for (int j = 0; j < 4; j++)
#pragma unroll
            for (int c = 0; c < 4; c++) acc[i][j][c] = 0.0f;

    GEMM_MAINLOOP(Ah, Al, Wh, Wl, acc, sg, tid, m0, n0, wm, wn, lane)

    // stage fp32 accumulators
    float* Sf = (float*)sg;
    __syncthreads();
#pragma unroll
    for (int mi = 0; mi < 4; mi++)
#pragma unroll
        for (int ni = 0; ni < 4; ni++) {
            const int rl = wm * 64 + mi * 16 + (lane >> 2);
            const int c0 = wn * 32 + ni * 8 + (lane & 3) * 2;
            *(float2*)(Sf + rl * FST + c0) =
                make_float2(acc[mi][ni][0], acc[mi][ni][1]);
            *(float2*)(Sf + (rl + 8) * FST + c0) =
                make_float2(acc[mi][ni][2], acc[mi][ni][3]);
        }
    __syncthreads();

    __nv_bfloat16* Oh = outs.hi[zi];
    __nv_bfloat16* Ol = outs.lo[zi];
    const bool dorope = (zi != 4);
    for (int it = tid; it < 2048; it += 256) {
        const int r  = it >> 4;          // 0..127
        const int c8 = (it & 15) * 8;    // 0..120
        float xt[8];
        *(float4*)(xt)     = *(const float4*)(Sf + r * FST + c8);
        *(float4*)(xt + 4) = *(const float4*)(Sf + r * FST + c8 + 4);
        float y[8];
        if (dorope) {
            const bool first = (c8 & 32) == 0;   // lower half of 64-wide head
            const int po = first ? 32 : -32;
            float xp[8];
            *(float4*)(xp)     = *(const float4*)(Sf + r * FST + c8 + po);
            *(float4*)(xp + 4) = *(const float4*)(Sf + r * FST + c8 + po + 4);
            const int t  = (m0 + r) & (TT - 1);
            const int ib = c8 & 31;
#pragma unroll
            for (int j = 0; j < 8; j++) {
                const float2 cc = cs[t * 32 + ib + j];
                y[j] = first ? fmaf(xt[j], cc.x, xp[j] * cc.y)
                             : fmaf(-xp[j], cc.y, xt[j] * cc.x);
            }
        } else {
#pragma unroll
            for (int j = 0; j < 8; j++) y[j] = xt[j];
        }
        unsigned short h[8], l[8];
#pragma unroll
        for (int j = 0; j < 8; j++) fsplit(y[j], h[j], l[j]);
        const uint4 hv = make_uint4((uint32_t)h[1] << 16 | h[0],
                                    (uint32_t)h[3] << 16 | h[2],
                                    (uint32_t)h[5] << 16 | h[4],
                                    (uint32_t)h[7] << 16 | h[6]);
        const uint4 lv = make_uint4((uint32_t)l[1] << 16 | l[0],
                                    (uint32_t)l[3] << 16 | l[2],
                                    (uint32_t)l[5] << 16 | l[4],
                                    (uint32_t)l[7] << 16 | l[6]);
        const size_t go = (size_t)(m0 + r) * DD + n0 + c8;
        *(uint4*)(Oh + go) = hv;
        *(uint4*)(Ol + go) = lv;
    }
}

// ---------------------------------------------------------------------------
// Tensor-core causal bilinear attention (unchanged from round 10).
// ---------------------------------------------------------------------------
__global__ void __launch_bounds__(256, 1) attn_mma(
        const __nv_bfloat16* __restrict__ qh,  const __nv_bfloat16* __restrict__ ql,
        const __nv_bfloat16* __restrict__ q2h, const __nv_bfloat16* __restrict__ q2l,
        const __nv_bfloat16* __restrict__ kh,  const __nv_bfloat16* __restrict__ kl,
        const __nv_bfloat16* __restrict__ k2h, const __nv_bfloat16* __restrict__ k2l,
        const __nv_bfloat16* __restrict__ vh,  const __nv_bfloat16* __restrict__ vl,
        __nv_bfloat16* __restrict__ zh, __nv_bfloat16* __restrict__ zl) {
    extern __shared__ __nv_bfloat16 sb2[];
    const int tid  = threadIdx.x;
    const int lane = tid & 31;
    const int w    = tid >> 5;
    const int qb = (int)gridDim.x - 1 - (int)blockIdx.x;
    const int q0 = qb * 128;
    const int b  = blockIdx.y >> 4;
    const int h  = blockIdx.y & 15;
    const size_t bh_off = (size_t)b * TT * DD + h * DH;

    {
        const __nv_bfloat16* src[4] = {qh, ql, q2h, q2l};
#pragma unroll
        for (int a = 0; a < 4; a++) {
            __nv_bfloat16* dst = sb2 + a * 128 * KST;
            for (int i = tid; i < 1024; i += 256) {
                const int r = i >> 3, ck = (i & 7) * 8;
                cpa16(dst + r * KST + ck, src[a] + bh_off + (size_t)(q0 + r) * DD + ck);
            }
        }
        cpa_commit();
        cpa_wait0();
        __syncthreads();
    }

    uint32_t fqh[4][4], fql[4][4], fq2h[4][4], fq2l[4][4];
    {
        const int ar = w * 16 + (lane & 15);
        const int ak = (lane >> 4) * 8;
#pragma unroll
        for (int kf = 0; kf < 4; kf++) {
            ldmat_x4(fqh [kf], saddr(sb2 + 0 * 128 * KST + ar * KST + kf * 16 + ak));
            ldmat_x4(fql [kf], saddr(sb2 + 1 * 128 * KST + ar * KST + kf * 16 + ak));
            ldmat_x4(fq2h[kf], saddr(sb2 + 2 * 128 * KST + ar * KST + kf * 16 + ak));
            ldmat_x4(fq2l[kf], saddr(sb2 + 3 * 128 * KST + ar * KST + kf * 16 + ak));
        }
    }
    __syncthreads();

    float zacc[8][4];
#pragma unroll
    for (int i = 0; i < 8; i++)
#pragma unroll
        for (int j = 0; j < 4; j++) zacc[i][j] = 0.0f;

    const int nkv = 2 * qb + 2;
    const int br = (lane & 7) + ((lane >> 4) & 1) * 8;
    const int bk = ((lane >> 3) & 1) * 8;
    const float invd2 = 1.0f / ((float)DH * (float)DH);

    auto load_tile = [&](int kj, int buf) {
        __nv_bfloat16* base = sb2 + buf * STAGE;
        const int kv0 = kj * 64;
        const __nv_bfloat16* src[6] = {kh, kl, k2h, k2l, vh, vl};
#pragma unroll
        for (int a = 0; a < 6; a++) {
            __nv_bfloat16* dst = base + a * ATILE;
            for (int i = tid; i < 512; i += 256) {
                const int r = i >> 3, ck = (i & 7) * 8;
                cpa16(dst + r * KST + ck, src[a] + bh_off + (size_t)(kv0 + r) * DD + ck);
            }
        }
    };

    load_tile(0, 0);
    cpa_commit();

    for (int kj = 0; kj < nkv; kj++) {
        cpa_wait0();
        __syncthreads();
        if (kj + 1 < nkv) {
            load_tile(kj + 1, (kj + 1) & 1);
            cpa_commit();
        }

        const __nv_bfloat16* base = sb2 + (kj & 1) * STAGE;
        const int kv0 = kj * 64;
        const bool masked = (kv0 >= q0);

        uint32_t ph[8][2], pl[8][2];
#pragma unroll
        for (int g = 0; g < 4; g++) {
            float s1f[2][4], s2f[2][4];
#pragma unroll
            for (int p = 0; p < 2; p++)
#pragma unroll
                for (int e = 0; e < 4; e++) { s1f[p][e] = 0.0f; s2f[p][e] = 0.0f; }

#pragma unroll
            for (int kf = 0; kf < 4; kf++) {
                uint32_t kh_[4], kl_[4], k2h_[4], k2l_[4];
                const int off = (g * 16 + br) * KST + kf * 16 + bk;
                ldmat_x4(kh_,  saddr(base + 0 * ATILE + off));
                ldmat_x4(kl_,  saddr(base + 1 * ATILE + off));
                ldmat_x4(k2h_, saddr(base + 2 * ATILE + off));
                ldmat_x4(k2l_, saddr(base + 3 * ATILE + off));
#pragma unroll
                for (int p = 0; p < 2; p++) {
                    mma16816(s1f[p], fqh[kf],  kh_[p*2],  kh_[p*2+1]);
                    mma16816(s2f[p], fq2h[kf], k2h_[p*2], k2h_[p*2+1]);
                }
#pragma unroll
                for (int p = 0; p < 2; p++) {
                    mma16816(s1f[p], fqh[kf],  kl_[p*2],  kl_[p*2+1]);
                    mma16816(s2f[p], fq2h[kf], k2l_[p*2], k2l_[p*2+1]);
                }
#pragma unroll
                for (int p = 0; p < 2; p++) {
                    mma16816(s1f[p], fql[kf],  kh_[p*2],  kh_[p*2+1]);
                    mma16816(s2f[p], fq2l[kf], k2h_[p*2], k2h_[p*2+1]);
                }
            }
#pragma unroll
            for (int p = 0; p < 2; p++) {
                const int j = g * 2 + p;
                float pr[4];
#pragma unroll
                for (int e = 0; e < 4; e++) pr[e] = s1f[p][e] * s2f[p][e] * invd2;
                if (masked) {
                    const int qr = q0 + w * 16 + (lane >> 2);
                    const int kc = kv0 + j * 8 + (lane & 3) * 2;
                    if (kc     > qr)     pr[0] = 0.0f;
                    if (kc + 1 > qr)     pr[1] = 0.0f;
                    if (kc     > qr + 8) pr[2] = 0.0f;
                    if (kc + 1 > qr + 8) pr[3] = 0.0f;
                }
                unsigned short hh[4], ll[4];
#pragma unroll
                for (int e = 0; e < 4; e++) fsplit(pr[e], hh[e], ll[e]);
                ph[j][0] = (uint32_t)hh[1] << 16 | hh[0];
                ph[j][1] = (uint32_t)hh[3] << 16 | hh[2];
                pl[j][0] = (uint32_t)ll[1] << 16 | ll[0];
                pl[j][1] = (uint32_t)ll[3] << 16 | ll[2];
            }
        }

        const int vr_lane = ((lane >> 3) & 1) * 8 + (lane & 7);
        const int vc_lane = ((lane >> 4) & 1) * 8;
#pragma unroll
        for (int f = 0; f < 4; f++) {
            uint32_t ah[4] = {ph[2*f][0], ph[2*f][1], ph[2*f+1][0], ph[2*f+1][1]};
            uint32_t al[4] = {pl[2*f][0], pl[2*f][1], pl[2*f+1][0], pl[2*f+1][1]};
            uint32_t vh_[4][4], vl_[4][4];
#pragma unroll
            for (int gd = 0; gd < 4; gd++) {
                const int off = (f * 16 + vr_lane) * KST + gd * 16 + vc_lane;
                ldmat_x4_trans(vh_[gd], saddr(base + 4 * ATILE + off));
                ldmat_x4_trans(vl_[gd], saddr(base + 5 * ATILE + off));
            }
#pragma unroll
            for (int gd = 0; gd < 4; gd++)
#pragma unroll
                for (int p = 0; p < 2; p++)
                    mma16816(zacc[gd*2+p], ah, vh_[gd][p*2], vh_[gd][p*2+1]);
#pragma unroll
            for (int gd = 0; gd < 4; gd++)
#pragma unroll
                for (int p = 0; p < 2; p++)
                    mma16816(zacc[gd*2+p], ah, vl_[gd][p*2], vl_[gd][p*2+1]);
#pragma unroll
            for (int gd = 0; gd < 4; gd++)
#pragma unroll
                for (int p = 0; p < 2; p++)
                    mma16816(zacc[gd*2+p], al, vh_[gd][p*2], vh_[gd][p*2+1]);
        }
    }

    {
        const int r = q0 + w * 16 + (lane >> 2);
        const int c = (lane & 3) * 2;
#pragma unroll
        for (int nd = 0; nd < 8; nd++) {
            unsigned short h0, l0, h1, l1;
#pragma unroll
            for (int half = 0; half < 2; half++) {
                fsplit(zacc[nd][half * 2 + 0], h0, l0);
                fsplit(zacc[nd][half * 2 + 1], h1, l1);
                const size_t off = bh_off + (size_t)(r + half * 8) * DD + nd * 8 + c;
                *(uint32_t*)(zh + off) = (uint32_t)h1 << 16 | h0;
                *(uint32_t*)(zl + off) = (uint32_t)l1 << 16 | l0;
            }
        }
    }
}

// ---------------------------------------------------------------------------
extern "C" void kernel_launch(void* const* d_in, const int* in_sizes, int n_in,
                              void* d_out, int out_size) {
    const float* x     = (const float*)d_in[0];
    const float* Wq    = (const float*)d_in[1];
    const float* Wk    = (const float*)d_in[2];
    const float* Wq2   = (const float*)d_in[3];
    const float* Wk2   = (const float*)d_in[4];
    const float* Wv    = (const float*)d_in[5];
    const float* Wproj = (const float*)d_in[6];
    float* out = (float*)d_out;

    float2* cs;
    cudaGetSymbolAddress((void**)&cs, g_cs);

    __nv_bfloat16 *xh, *xl, *zh, *zl, *w6h, *w6l;
    cudaGetSymbolAddress((void**)&xh,  g_xh);  cudaGetSymbolAddress((void**)&xl,  g_xl);
    cudaGetSymbolAddress((void**)&zh,  g_zh);  cudaGetSymbolAddress((void**)&zl,  g_zl);
    cudaGetSymbolAddress((void**)&w6h, g_w6h); cudaGetSymbolAddress((void**)&w6l, g_w6l);

    __nv_bfloat16 *qh, *ql, *q2h, *q2l, *kh, *kl, *k2h, *k2l, *vh, *vl;
    cudaGetSymbolAddress((void**)&qh,  g_qh);  cudaGetSymbolAddress((void**)&ql,  g_ql);
    cudaGetSymbolAddress((void**)&q2h, g_q2h); cudaGetSymbolAddress((void**)&q2l, g_q2l);
    cudaGetSymbolAddress((void**)&kh,  g_kh);  cudaGetSymbolAddress((void**)&kl,  g_kl);
    cudaGetSymbolAddress((void**)&k2h, g_k2h); cudaGetSymbolAddress((void**)&k2l, g_k2l);
    cudaGetSymbolAddress((void**)&vh,  g_vh);  cudaGetSymbolAddress((void**)&vl,  g_vl);

    Outs outs;
    outs.hi[0] = qh;  outs.lo[0] = ql;
    outs.hi[1] = kh;  outs.lo[1] = kl;
    outs.hi[2] = q2h; outs.lo[2] = q2l;
    outs.hi[3] = k2h; outs.lo[3] = k2l;
    outs.hi[4] = vh;  outs.lo[4] = vl;

    cudaFuncSetAttribute(gemm_plain,
                         cudaFuncAttributeMaxDynamicSharedMemorySize, GEMM_SMEM);
    cudaFuncSetAttribute(gemm_rope,
                         cudaFuncAttributeMaxDynamicSharedMemorySize, GEMM_SMEM);

    // 0) cos/sin table
    build_cs<<<TT * 32 / 256, 256>>>(cs);

    // 1) split inputs
    split_f32<<<MM * DD / 1024, 256>>>(x, xh, xl);
    split_w6<<<dim3(DD * DD / 1024, 6), 256>>>(Wq, Wk, Wq2, Wk2, Wv, Wproj, w6h, w6l);

    // 2) five fused projections with vectorized RoPE + split epilogue
    gemm_rope<<<dim3(DD / 128, MM / 128, 5), 256, GEMM_SMEM>>>(
        xh, xl, w6h, w6l, outs, cs);

    // 3) attention (writes zh/zl directly)
    const int attn_smem = 2 * STAGE * (int)sizeof(__nv_bfloat16);
    cudaFuncSetAttribute(attn_mma,
                         cudaFuncAttributeMaxDynamicSharedMemorySize, attn_smem);
    attn_mma<<<dim3(TT / 128, BB * HH), 256, attn_smem>>>(
        qh, ql, q2h, q2l, kh, kl, k2h, k2l, vh, vl, zh, zl);

    // 4) output projection (round-10-identical plain kernel)
    gemm_plain<<<dim3(DD / 128, MM / 128, 1), 256, GEMM_SMEM>>>(
        zh, zl, w6h + (size_t)5 * DD * DD, w6l + (size_t)5 * DD * DD, out);
}

// round 14
// speedup vs baseline: 1.1335x; 1.0163x over previous
#include <cuda_runtime.h>
#include <cuda_bf16.h>
#include <math.h>
#include <stdint.h>

#define BB 2
#define TT 2048
#define DD 1024
#define HH 16
#define DH 64
#define MM (BB*TT)

/* ---- gemm geometry: CTA 128x128, 8 warps (64x32), k-chunk 32, 2-stage,
       80KB smem -> 2 CTAs/SM ---- */
#define GST 40
#define GTILE (128*GST)
#define GSTAGE (4*GTILE)            /* 20480 bf16 = 40960 B per stage */
#define NSTG 2
#define NCH  32                     /* 1024 / 32 */
#define GEMM_SMEM (NSTG*GSTAGE*2)   /* 81920 B */
#define FST 132                     /* fp32 staging stride (floats) */

#define KST 72
#define ATILE (64*KST)
#define STAGE (6*ATILE)

// ---------------- scratch (device globals) ----------------------------------
__device__ float2 g_cs[TT*32];
__device__ __nv_bfloat16 g_xh [MM*DD], g_xl [MM*DD];
__device__ __nv_bfloat16 g_zh [MM*DD], g_zl [MM*DD];
__device__ __nv_bfloat16 g_w6h[6*DD*DD], g_w6l[6*DD*DD];
__device__ __nv_bfloat16 g_qh [MM*DD], g_ql [MM*DD];
__device__ __nv_bfloat16 g_q2h[MM*DD], g_q2l[MM*DD];
__device__ __nv_bfloat16 g_kh [MM*DD], g_kl [MM*DD];
__device__ __nv_bfloat16 g_k2h[MM*DD], g_k2l[MM*DD];
__device__ __nv_bfloat16 g_vh [MM*DD], g_vl [MM*DD];

struct Outs { __nv_bfloat16* hi[5]; __nv_bfloat16* lo[5]; };

// ---------------------------------------------------------------------------
__device__ __forceinline__ uint32_t saddr(const void* p) {
    return (uint32_t)__cvta_generic_to_shared(p);
}
__device__ __forceinline__ void ldmat_x4(uint32_t (&r)[4], uint32_t a) {
    asm volatile("ldmatrix.sync.aligned.m8n8.x4.shared.b16 {%0,%1,%2,%3}, [%4];"
                 : "=r"(r[0]), "=r"(r[1]), "=r"(r[2]), "=r"(r[3]) : "r"(a));
}
__device__ __forceinline__ void ldmat_x4_trans(uint32_t (&r)[4], uint32_t a) {
    asm volatile("ldmatrix.sync.aligned.m8n8.x4.trans.shared.b16 {%0,%1,%2,%3}, [%4];"
                 : "=r"(r[0]), "=r"(r[1]), "=r"(r[2]), "=r"(r[3]) : "r"(a));
}
__device__ __forceinline__ void mma16816(float (&d)[4], const uint32_t (&a)[4],
                                         uint32_t b0, uint32_t b1) {
    asm volatile(
        "mma.sync.aligned.m16n8k16.row.col.f32.bf16.bf16.f32 "
        "{%0,%1,%2,%3}, {%4,%5,%6,%7}, {%8,%9}, {%0,%1,%2,%3};"
        : "+f"(d[0]), "+f"(d[1]), "+f"(d[2]), "+f"(d[3])
        : "r"(a[0]), "r"(a[1]), "r"(a[2]), "r"(a[3]), "r"(b0), "r"(b1));
}
__device__ __forceinline__ void cpa16(void* dst, const void* src) {
    asm volatile("cp.async.cg.shared.global [%0], [%1], 16;"
                 :: "r"(saddr(dst)), "l"(src));
}
__device__ __forceinline__ void cpa_commit() { asm volatile("cp.async.commit_group;"); }
__device__ __forceinline__ void cpa_wait0()  { asm volatile("cp.async.wait_group 0;"); }
__device__ __forceinline__ void cpa_wait1()  { asm volatile("cp.async.wait_group 1;"); }

__device__ __forceinline__ void fsplit(float x, unsigned short& h, unsigned short& l) {
    __nv_bfloat16 hb = __float2bfloat16_rn(x);
    __nv_bfloat16 lb = __float2bfloat16_rn(x - __bfloat162float(hb));
    h = __bfloat16_as_ushort(hb);
    l = __bfloat16_as_ushort(lb);
}

// ---------------------------------------------------------------------------
// cos/sin table (bit-identical expressions to the original rope)
// ---------------------------------------------------------------------------
__global__ void build_cs(float2* cs) {
    const int idx = blockIdx.x * 256 + threadIdx.x;
    const int t = idx >> 5;
    const int i = idx & 31;
    const float inv_freq = powf(10000.0f, -(float)i * (1.0f / 32.0f));
    float c, s;
    sincosf((float)t * inv_freq, &s, &c);
    cs[idx] = make_float2(c, s);
}

// ---------------------------------------------------------------------------
// splits
// ---------------------------------------------------------------------------
__global__ void split_f32(const float* __restrict__ in,
                          __nv_bfloat16* __restrict__ hi,
                          __nv_bfloat16* __restrict__ lo) {
    const size_t i = ((size_t)blockIdx.x * 256 + threadIdx.x) * 4;
    float4 v = *(const float4*)(in + i);
    float f[4] = {v.x, v.y, v.z, v.w};
    unsigned short h[4], l[4];
#pragma unroll
    for (int e = 0; e < 4; e++) fsplit(f[e], h[e], l[e]);
    *(uint2*)(hi + i) = make_uint2((uint32_t)h[1] << 16 | h[0],
                                   (uint32_t)h[3] << 16 | h[2]);
    *(uint2*)(lo + i) = make_uint2((uint32_t)l[1] << 16 | l[0],
                                   (uint32_t)l[3] << 16 | l[2]);
}

__global__ void split_w6(const float* __restrict__ w0, const float* __restrict__ w1,
                         const float* __restrict__ w2, const float* __restrict__ w3,
                         const float* __restrict__ w4, const float* __restrict__ w5,
                         __nv_bfloat16* __restrict__ hi, __nv_bfloat16* __restrict__ lo) {
    const float* src[6] = {w0, w1, w2, w3, w4, w5};
    const float* in = src[blockIdx.y];
    const size_t off = (size_t)blockIdx.y * DD * DD;
    const size_t i = ((size_t)blockIdx.x * 256 + threadIdx.x) * 4;
    float4 v = *(const float4*)(in + i);
    float f[4] = {v.x, v.y, v.z, v.w};
    unsigned short h[4], l[4];
#pragma unroll
    for (int e = 0; e < 4; e++) fsplit(f[e], h[e], l[e]);
    *(uint2*)(hi + off + i) = make_uint2((uint32_t)h[1] << 16 | h[0],
                                         (uint32_t)h[3] << 16 | h[2]);
    *(uint2*)(lo + off + i) = make_uint2((uint32_t)l[1] << 16 | l[0],
                                         (uint32_t)l[3] << 16 | l[2]);
}

// ---------------------------------------------------------------------------
// shared double-buffered mainloop (k-chunk 32, 2 stages, occ 2)
// ---------------------------------------------------------------------------
#define GEMM_MAINLOOP(Ah, Al, Wh, Wl, acc, sg, tid, m0, n0, wm, wn, lane)      \
    auto load_chunk = [&](int c) {                                             \
        __nv_bfloat16* base = sg + (c & 1) * GSTAGE;                           \
        const int k0 = c * 32;                                                 \
        _Pragma("unroll 2")                                                    \
        for (int i = tid; i < 512; i += 256) {                                 \
            const int r  = i >> 2;                                             \
            const int ck = (i & 3) * 8;                                        \
            const int so = r * GST + ck;                                       \
            cpa16(base + 0 * GTILE + so, Ah + (size_t)(m0 + r) * DD + k0 + ck);\
            cpa16(base + 1 * GTILE + so, Al + (size_t)(m0 + r) * DD + k0 + ck);\
            cpa16(base + 2 * GTILE + so, Wh + (size_t)(n0 + r) * DD + k0 + ck);\
            cpa16(base + 3 * GTILE + so, Wl + (size_t)(n0 + r) * DD + k0 + ck);\
        }                                                                      \
        cpa_commit();                                                          \
    };                                                                         \
    load_chunk(0);                                                             \
    for (int ch = 0; ch < NCH; ch++) {                                         \
        if (ch + 1 < NCH) { load_chunk(ch + 1); cpa_wait1(); }                 \
        else              cpa_wait0();                                         \
        __syncthreads();                                                       \
        const __nv_bfloat16* cur = sg + (ch & 1) * GSTAGE;                     \
        const __nv_bfloat16* Ahi = cur;                                        \
        const __nv_bfloat16* Alo = cur + GTILE;                                \
        const __nv_bfloat16* Bhi = cur + 2 * GTILE;                            \
        const __nv_bfloat16* Blo = cur + 3 * GTILE;                            \
        _Pragma("unroll")                                                      \
        for (int kk = 0; kk < 2; kk++) {                                       \
            uint32_t ahi[4][4], alo[4][4], bhi[2][4], blo[2][4];               \
            const int ar = wm * 64 + (lane & 15);                              \
            const int ak = kk * 16 + (lane >> 4) * 8;                          \
            _Pragma("unroll")                                                  \
            for (int mi = 0; mi < 4; mi++) {                                   \
                ldmat_x4(ahi[mi], saddr(Ahi + (ar + mi * 16) * GST + ak));     \
                ldmat_x4(alo[mi], saddr(Alo + (ar + mi * 16) * GST + ak));     \
            }                                                                  \
            const int br = wn * 32 + ((lane >> 4) & 1) * 8 + (lane & 7);       \
            const int bk = kk * 16 + ((lane >> 3) & 1) * 8;                    \
            _Pragma("unroll")                                                  \
            for (int p = 0; p < 2; p++) {                                      \
                ldmat_x4(bhi[p], saddr(Bhi + (br + p * 16) * GST + bk));       \
                ldmat_x4(blo[p], saddr(Blo + (br + p * 16) * GST + bk));       \
            }                                                                  \
            _Pragma("unroll")                                                  \
            for (int mi = 0; mi < 4; mi++)                                     \
                _Pragma("unroll")                                              \
                for (int ni = 0; ni < 4; ni++) {                               \
                    const uint32_t* bh = &bhi[ni >> 1][(ni & 1) * 2];          \
                    mma16816(acc[mi][ni], ahi[mi], bh[0], bh[1]);              \
                }                                                              \
            _Pragma("unroll")                                                  \
            for (int mi = 0; mi < 4; mi++)                                     \
                _Pragma("unroll")                                              \
                for (int ni = 0; ni < 4; ni++) {                               \
                    const uint32_t* bl = &blo[ni >> 1][(ni & 1) * 2];          \
                    mma16816(acc[mi][ni], ahi[mi], bl[0], bl[1]);              \
                }                                                              \
            _Pragma("unroll")                                                  \
            for (int mi = 0; mi < 4; mi++)                                     \
                _Pragma("unroll")                                              \
                for (int ni = 0; ni < 4; ni++) {                               \
                    const uint32_t* bh = &bhi[ni >> 1][(ni & 1) * 2];          \
                    mma16816(acc[mi][ni], alo[mi], bh[0], bh[1]);              \
                }                                                              \
        }                                                                      \
        __syncthreads();                                                       \
    }

// ---------------------------------------------------------------------------
// out-projection: plain fp32 epilogue
// ---------------------------------------------------------------------------
__global__ void __launch_bounds__(256, 2) gemm_plain(
        const __nv_bfloat16* __restrict__ Ah, const __nv_bfloat16* __restrict__ Al,
        const __nv_bfloat16* __restrict__ Wh, const __nv_bfloat16* __restrict__ Wl,
        float* __restrict__ C) {
    extern __shared__ __nv_bfloat16 sg[];
    const int tid  = threadIdx.x;
    const int wid  = tid >> 5;
    const int lane = tid & 31;
    const int m0 = blockIdx.y * 128;
    const int n0 = blockIdx.x * 128;
    const int wm = wid & 1;
    const int wn = wid >> 1;

    float acc[4][4][4];
#pragma unroll
    for (int i = 0; i < 4; i++)
#pragma unroll
        for (int j = 0; j < 4; j++)
#pragma unroll
            for (int c = 0; c < 4; c++) acc[i][j][c] = 0.0f;

    GEMM_MAINLOOP(Ah, Al, Wh, Wl, acc, sg, tid, m0, n0, wm, wn, lane)

#pragma unroll
    for (int mi = 0; mi < 4; mi++)
#pragma unroll
        for (int ni = 0; ni < 4; ni++) {
            const int r0 = m0 + wm * 64 + mi * 16 + (lane >> 2);
            const int c0 = n0 + wn * 32 + ni * 8 + (lane & 3) * 2;
            *(float2*)(C + (size_t)r0 * 1024 + c0) =
                make_float2(acc[mi][ni][0], acc[mi][ni][1]);
            *(float2*)(C + (size_t)(r0 + 8) * 1024 + c0) =
                make_float2(acc[mi][ni][2], acc[mi][ni][3]);
        }
}

// ---------------------------------------------------------------------------
// projections: fused vectorized RoPE + hi/lo split epilogue
// ---------------------------------------------------------------------------
__global__ void __launch_bounds__(256, 2) gemm_rope(
        const __nv_bfloat16* __restrict__ Ah, const __nv_bfloat16* __restrict__ Al,
        const __nv_bfloat16* __restrict__ Wh, const __nv_bfloat16* __restrict__ Wl,
        Outs outs, const float2* __restrict__ cs) {
    extern __shared__ __nv_bfloat16 sg[];
    const int zi = blockIdx.z;
    Wh += (size_t)zi * DD * DD;
    Wl += (size_t)zi * DD * DD;

    const int tid  = threadIdx.x;
    const int wid  = tid >> 5;
    const int lane = tid & 31;
    const int m0 = blockIdx.y * 128;
    const int n0 = blockIdx.x * 128;
    const int wm = wid & 1;
    const int wn = wid >> 1;

    float acc[4][4][4];
#pragma unroll
    for (int i = 0; i < 4; i++)
#pragma unroll
        for (int j = 0; j < 4; j++)
#pragma unroll
            for (int c = 0; c < 4; c++) acc[i][j][c] = 0.0f;

    GEMM_MAINLOOP(Ah, Al, Wh, Wl, acc, sg, tid, m0, n0, wm, wn, lane)

    // stage fp32 accumulators (67.6 KB fits in the 80 KB smem region)
    float* Sf = (float*)sg;
    __syncthreads();
#pragma unroll
    for (int mi = 0; mi < 4; mi++)
#pragma unroll
        for (int ni = 0; ni < 4; ni++) {
            const int rl = wm * 64 + mi * 16 + (lane >> 2);
            const int c0 = wn * 32 + ni * 8 + (lane & 3) * 2;
            *(float2*)(Sf + rl * FST + c0) =
                make_float2(acc[mi][ni][0], acc[mi][ni][1]);
            *(float2*)(Sf + (rl + 8) * FST + c0) =
                make_float2(acc[mi][ni][2], acc[mi][ni][3]);
        }
    __syncthreads();

    __nv_bfloat16* Oh = outs.hi[zi];
    __nv_bfloat16* Ol = outs.lo[zi];
    const bool dorope = (zi != 4);
    for (int it = tid; it < 2048; it += 256) {
        const int r  = it >> 4;
        const int c8 = (it & 15) * 8;
        float xt[8];
        *(float4*)(xt)     = *(const float4*)(Sf + r * FST + c8);
        *(float4*)(xt + 4) = *(const float4*)(Sf + r * FST + c8 + 4);
        float y[8];
        if (dorope) {
            const bool first = (c8 & 32) == 0;
            const int po = first ? 32 : -32;
            float xp[8];
            *(float4*)(xp)     = *(const float4*)(Sf + r * FST + c8 + po);
            *(float4*)(xp + 4) = *(const float4*)(Sf + r * FST + c8 + po + 4);
            const int t  = (m0 + r) & (TT - 1);
            const int ib = c8 & 31;
#pragma unroll
            for (int j = 0; j < 8; j++) {
                const float2 cc = cs[t * 32 + ib + j];
                y[j] = first ? fmaf(xt[j], cc.x, xp[j] * cc.y)
                             : fmaf(-xp[j], cc.y, xt[j] * cc.x);
            }
        } else {
#pragma unroll
            for (int j = 0; j < 8; j++) y[j] = xt[j];
        }
        unsigned short h[8], l[8];
#pragma unroll
        for (int j = 0; j < 8; j++) fsplit(y[j], h[j], l[j]);
        const uint4 hv = make_uint4((uint32_t)h[1] << 16 | h[0],
                                    (uint32_t)h[3] << 16 | h[2],
                                    (uint32_t)h[5] << 16 | h[4],
                                    (uint32_t)h[7] << 16 | h[6]);
        const uint4 lv = make_uint4((uint32_t)l[1] << 16 | l[0],
                                    (uint32_t)l[3] << 16 | l[2],
                                    (uint32_t)l[5] << 16 | l[4],
                                    (uint32_t)l[7] << 16 | l[6]);
        const size_t go = (size_t)(m0 + r) * DD + n0 + c8;
        *(uint4*)(Oh + go) = hv;
        *(uint4*)(Ol + go) = lv;
    }
}

// ---------------------------------------------------------------------------
// Tensor-core causal bilinear attention (unchanged from round 10).
// ---------------------------------------------------------------------------
__global__ void __launch_bounds__(256, 1) attn_mma(
        const __nv_bfloat16* __restrict__ qh,  const __nv_bfloat16* __restrict__ ql,
        const __nv_bfloat16* __restrict__ q2h, const __nv_bfloat16* __restrict__ q2l,
        const __nv_bfloat16* __restrict__ kh,  const __nv_bfloat16* __restrict__ kl,
        const __nv_bfloat16* __restrict__ k2h, const __nv_bfloat16* __restrict__ k2l,
        const __nv_bfloat16* __restrict__ vh,  const __nv_bfloat16* __restrict__ vl,
        __nv_bfloat16* __restrict__ zh, __nv_bfloat16* __restrict__ zl) {
    extern __shared__ __nv_bfloat16 sb2[];
    const int tid  = threadIdx.x;
    const int lane = tid & 31;
    const int w    = tid >> 5;
    const int qb = (int)gridDim.x - 1 - (int)blockIdx.x;
    const int q0 = qb * 128;
    const int b  = blockIdx.y >> 4;
    const int h  = blockIdx.y & 15;
    const size_t bh_off = (size_t)b * TT * DD + h * DH;

    {
        const __nv_bfloat16* src[4] = {qh, ql, q2h, q2l};
#pragma unroll
        for (int a = 0; a < 4; a++) {
            __nv_bfloat16* dst = sb2 + a * 128 * KST;
            for (int i = tid; i < 1024; i += 256) {
                const int r = i >> 3, ck = (i & 7) * 8;
                cpa16(dst + r * KST + ck, src[a] + bh_off + (size_t)(q0 + r) * DD + ck);
            }
        }
        cpa_commit();
        cpa_wait0();
        __syncthreads();
    }

    uint32_t fqh[4][4], fql[4][4], fq2h[4][4], fq2l[4][4];
    {
        const int ar = w * 16 + (lane & 15);
        const int ak = (lane >> 4) * 8;
#pragma unroll
        for (int kf = 0; kf < 4; kf++) {
            ldmat_x4(fqh [kf], saddr(sb2 + 0 * 128 * KST + ar * KST + kf * 16 + ak));
            ldmat_x4(fql [kf], saddr(sb2 + 1 * 128 * KST + ar * KST + kf * 16 + ak));
            ldmat_x4(fq2h[kf], saddr(sb2 + 2 * 128 * KST + ar * KST + kf * 16 + ak));
            ldmat_x4(fq2l[kf], saddr(sb2 + 3 * 128 * KST + ar * KST + kf * 16 + ak));
        }
    }
    __syncthreads();

    float zacc[8][4];
#pragma unroll
    for (int i = 0; i < 8; i++)
#pragma unroll
        for (int j = 0; j < 4; j++) zacc[i][j] = 0.0f;

    const int nkv = 2 * qb + 2;
    const int br = (lane & 7) + ((lane >> 4) & 1) * 8;
    const int bk = ((lane >> 3) & 1) * 8;
    const float invd2 = 1.0f / ((float)DH * (float)DH);

    auto load_tile = [&](int kj, int buf) {
        __nv_bfloat16* base = sb2 + buf * STAGE;
        const int kv0 = kj * 64;
        const __nv_bfloat16* src[6] = {kh, kl, k2h, k2l, vh, vl};
#pragma unroll
        for (int a = 0; a < 6; a++) {
            __nv_bfloat16* dst = base + a * ATILE;
            for (int i = tid; i < 512; i += 256) {
                const int r = i >> 3, ck = (i & 7) * 8;
                cpa16(dst + r * KST + ck, src[a] + bh_off + (size_t)(kv0 + r) * DD + ck);
            }
        }
    };

    load_tile(0, 0);
    cpa_commit();

    for (int kj = 0; kj < nkv; kj++) {
        cpa_wait0();
        __syncthreads();
        if (kj + 1 < nkv) {
            load_tile(kj + 1, (kj + 1) & 1);
            cpa_commit();
        }

        const __nv_bfloat16* base = sb2 + (kj & 1) * STAGE;
        const int kv0 = kj * 64;
        const bool masked = (kv0 >= q0);

        uint32_t ph[8][2], pl[8][2];
#pragma unroll
        for (int g = 0; g < 4; g++) {
            float s1f[2][4], s2f[2][4];
#pragma unroll
            for (int p = 0; p < 2; p++)
#pragma unroll
                for (int e = 0; e < 4; e++) { s1f[p][e] = 0.0f; s2f[p][e] = 0.0f; }

#pragma unroll
            for (int kf = 0; kf < 4; kf++) {
                uint32_t kh_[4], kl_[4], k2h_[4], k2l_[4];
                const int off = (g * 16 + br) * KST + kf * 16 + bk;
                ldmat_x4(kh_,  saddr(base + 0 * ATILE + off));
                ldmat_x4(kl_,  saddr(base + 1 * ATILE + off));
                ldmat_x4(k2h_, saddr(base + 2 * ATILE + off));
                ldmat_x4(k2l_, saddr(base + 3 * ATILE + off));
#pragma unroll
                for (int p = 0; p < 2; p++) {
                    mma16816(s1f[p], fqh[kf],  kh_[p*2],  kh_[p*2+1]);
                    mma16816(s2f[p], fq2h[kf], k2h_[p*2], k2h_[p*2+1]);
                }
#pragma unroll
                for (int p = 0; p < 2; p++) {
                    mma16816(s1f[p], fqh[kf],  kl_[p*2],  kl_[p*2+1]);
                    mma16816(s2f[p], fq2h[kf], k2l_[p*2], k2l_[p*2+1]);
                }
#pragma unroll
                for (int p = 0; p < 2; p++) {
                    mma16816(s1f[p], fql[kf],  kh_[p*2],  kh_[p*2+1]);
                    mma16816(s2f[p], fq2l[kf], k2h_[p*2], k2h_[p*2+1]);
                }
            }
#pragma unroll
            for (int p = 0; p < 2; p++) {
                const int j = g * 2 + p;
                float pr[4];
#pragma unroll
                for (int e = 0; e < 4; e++) pr[e] = s1f[p][e] * s2f[p][e] * invd2;
                if (masked) {
                    const int qr = q0 + w * 16 + (lane >> 2);
                    const int kc = kv0 + j * 8 + (lane & 3) * 2;
                    if (kc     > qr)     pr[0] = 0.0f;
                    if (kc + 1 > qr)     pr[1] = 0.0f;
                    if (kc     > qr + 8) pr[2] = 0.0f;
                    if (kc + 1 > qr + 8) pr[3] = 0.0f;
                }
                unsigned short hh[4], ll[4];
#pragma unroll
                for (int e = 0; e < 4; e++) fsplit(pr[e], hh[e], ll[e]);
                ph[j][0] = (uint32_t)hh[1] << 16 | hh[0];
                ph[j][1] = (uint32_t)hh[3] << 16 | hh[2];
                pl[j][0] = (uint32_t)ll[1] << 16 | ll[0];
                pl[j][1] = (uint32_t)ll[3] << 16 | ll[2];
            }
        }

        const int vr_lane = ((lane >> 3) & 1) * 8 + (lane & 7);
        const int vc_lane = ((lane >> 4) & 1) * 8;
#pragma unroll
        for (int f = 0; f < 4; f++) {
            uint32_t ah[4] = {ph[2*f][0], ph[2*f][1], ph[2*f+1][0], ph[2*f+1][1]};
            uint32_t al[4] = {pl[2*f][0], pl[2*f][1], pl[2*f+1][0], pl[2*f+1][1]};
            uint32_t vh_[4][4], vl_[4][4];
#pragma unroll
            for (int gd = 0; gd < 4; gd++) {
                const int off = (f * 16 + vr_lane) * KST + gd * 16 + vc_lane;
                ldmat_x4_trans(vh_[gd], saddr(base + 4 * ATILE + off));
                ldmat_x4_trans(vl_[gd], saddr(base + 5 * ATILE + off));
            }
#pragma unroll
            for (int gd = 0; gd < 4; gd++)
#pragma unroll
                for (int p = 0; p < 2; p++)
                    mma16816(zacc[gd*2+p], ah, vh_[gd][p*2], vh_[gd][p*2+1]);
#pragma unroll
            for (int gd = 0; gd < 4; gd++)
#pragma unroll
                for (int p = 0; p < 2; p++)
                    mma16816(zacc[gd*2+p], ah, vl_[gd][p*2], vl_[gd][p*2+1]);
#pragma unroll
            for (int gd = 0; gd < 4; gd++)
#pragma unroll
                for (int p = 0; p < 2; p++)
                    mma16816(zacc[gd*2+p], al, vh_[gd][p*2], vh_[gd][p*2+1]);
        }
    }

    {
        const int r = q0 + w * 16 + (lane >> 2);
        const int c = (lane & 3) * 2;
#pragma unroll
        for (int nd = 0; nd < 8; nd++) {
            unsigned short h0, l0, h1, l1;
#pragma unroll
            for (int half = 0; half < 2; half++) {
                fsplit(zacc[nd][half * 2 + 0], h0, l0);
                fsplit(zacc[nd][half * 2 + 1], h1, l1);
                const size_t off = bh_off + (size_t)(r + half * 8) * DD + nd * 8 + c;
                *(uint32_t*)(zh + off) = (uint32_t)h1 << 16 | h0;
                *(uint32_t*)(zl + off) = (uint32_t)l1 << 16 | l0;
            }
        }
    }
}

// ---------------------------------------------------------------------------
extern "C" void kernel_launch(void* const* d_in, const int* in_sizes, int n_in,
                              void* d_out, int out_size) {
    const float* x     = (const float*)d_in[0];
    const float* Wq    = (const float*)d_in[1];
    const float* Wk    = (const float*)d_in[2];
    const float* Wq2   = (const float*)d_in[3];
    const float* Wk2   = (const float*)d_in[4];
    const float* Wv    = (const float*)d_in[5];
    const float* Wproj = (const float*)d_in[6];
    float* out = (float*)d_out;

    float2* cs;
    cudaGetSymbolAddress((void**)&cs, g_cs);

    __nv_bfloat16 *xh, *xl, *zh, *zl, *w6h, *w6l;
    cudaGetSymbolAddress((void**)&xh,  g_xh);  cudaGetSymbolAddress((void**)&xl,  g_xl);
    cudaGetSymbolAddress((void**)&zh,  g_zh);  cudaGetSymbolAddress((void**)&zl,  g_zl);
    cudaGetSymbolAddress((void**)&w6h, g_w6h); cudaGetSymbolAddress((void**)&w6l, g_w6l);

    __nv_bfloat16 *qh, *ql, *q2h, *q2l, *kh, *kl, *k2h, *k2l, *vh, *vl;
    cudaGetSymbolAddress((void**)&qh,  g_qh);  cudaGetSymbolAddress((void**)&ql,  g_ql);
    cudaGetSymbolAddress((void**)&q2h, g_q2h); cudaGetSymbolAddress((void**)&q2l, g_q2l);
    cudaGetSymbolAddress((void**)&kh,  g_kh);  cudaGetSymbolAddress((void**)&kl,  g_kl);
    cudaGetSymbolAddress((void**)&k2h, g_k2h); cudaGetSymbolAddress((void**)&k2l, g_k2l);
    cudaGetSymbolAddress((void**)&vh,  g_vh);  cudaGetSymbolAddress((void**)&vl,  g_vl);

    Outs outs;
    outs.hi[0] = qh;  outs.lo[0] = ql;
    outs.hi[1] = kh;  outs.lo[1] = kl;
    outs.hi[2] = q2h; outs.lo[2] = q2l;
    outs.hi[3] = k2h; outs.lo[3] = k2l;
    outs.hi[4] = vh;  outs.lo[4] = vl;

    cudaFuncSetAttribute(gemm_plain,
                         cudaFuncAttributeMaxDynamicSharedMemorySize, GEMM_SMEM);
    cudaFuncSetAttribute(gemm_rope,
                         cudaFuncAttributeMaxDynamicSharedMemorySize, GEMM_SMEM);

    // 0) cos/sin table
    build_cs<<<TT * 32 / 256, 256>>>(cs);

    // 1) split inputs
    split_f32<<<MM * DD / 1024, 256>>>(x, xh, xl);
    split_w6<<<dim3(DD * DD / 1024, 6), 256>>>(Wq, Wk, Wq2, Wk2, Wv, Wproj, w6h, w6l);

    // 2) five fused projections, 2 CTAs/SM
    gemm_rope<<<dim3(DD / 128, MM / 128, 5), 256, GEMM_SMEM>>>(
        xh, xl, w6h, w6l, outs, cs);

    // 3) attention (writes zh/zl directly)
    const int attn_smem = 2 * STAGE * (int)sizeof(__nv_bfloat16);
    cudaFuncSetAttribute(attn_mma,
                         cudaFuncAttributeMaxDynamicSharedMemorySize, attn_smem);
    attn_mma<<<dim3(TT / 128, BB * HH), 256, attn_smem>>>(
        qh, ql, q2h, q2l, kh, kl, k2h, k2l, vh, vl, zh, zl);

    // 4) output projection, 2 CTAs/SM
    gemm_plain<<<dim3(DD / 128, MM / 128, 1), 256, GEMM_SMEM>>>(
        zh, zl, w6h + (size_t)5 * DD * DD, w6l + (size_t)5 * DD * DD, out);
}

// round 15
// speedup vs baseline: 1.2473x; 1.1004x over previous
#include <cuda_runtime.h>
#include <cuda_bf16.h>
#include <math.h>
#include <stdint.h>

#define BB 2
#define TT 2048
#define DD 1024
#define HH 16
#define DH 64
#define MM (BB*TT)

/* ---- gemm geometry: CTA 128x128, 8 warps (64x32), k-chunk 32,
       SW64-swizzled 64B rows, 3 stages, 96KB smem -> 2 CTAs/SM ---- */
#define GTILE_B 8192u               /* 128 rows x 64 B */
#define GSTAGE_B (4u*GTILE_B)       /* Ah,Al,Wh,Wl = 32 KB */
#define NSTG 3
#define NCH  32                     /* 1024 / 32 */
#define GEMM_SMEM (NSTG*GSTAGE_B)   /* 98304 B */
#define FST 132                     /* fp32 staging stride (floats) */

#define KST 72
#define ATILE (64*KST)
#define STAGE (6*ATILE)

// ---------------- scratch (device globals) ----------------------------------
__device__ float2 g_cs[TT*32];
__device__ __nv_bfloat16 g_xh [MM*DD], g_xl [MM*DD];
__device__ __nv_bfloat16 g_zh [MM*DD], g_zl [MM*DD];
__device__ __nv_bfloat16 g_w6h[6*DD*DD], g_w6l[6*DD*DD];
__device__ __nv_bfloat16 g_qh [MM*DD], g_ql [MM*DD];
__device__ __nv_bfloat16 g_q2h[MM*DD], g_q2l[MM*DD];
__device__ __nv_bfloat16 g_kh [MM*DD], g_kl [MM*DD];
__device__ __nv_bfloat16 g_k2h[MM*DD], g_k2l[MM*DD];
__device__ __nv_bfloat16 g_vh [MM*DD], g_vl [MM*DD];

struct Outs { __nv_bfloat16* hi[5]; __nv_bfloat16* lo[5]; };

// ---------------------------------------------------------------------------
__device__ __forceinline__ uint32_t saddr(const void* p) {
    return (uint32_t)__cvta_generic_to_shared(p);
}
__device__ __forceinline__ void ldmat_x4(uint32_t (&r)[4], uint32_t a) {
    asm volatile("ldmatrix.sync.aligned.m8n8.x4.shared.b16 {%0,%1,%2,%3}, [%4];"
                 : "=r"(r[0]), "=r"(r[1]), "=r"(r[2]), "=r"(r[3]) : "r"(a));
}
__device__ __forceinline__ void ldmat_x4_trans(uint32_t (&r)[4], uint32_t a) {
    asm volatile("ldmatrix.sync.aligned.m8n8.x4.trans.shared.b16 {%0,%1,%2,%3}, [%4];"
                 : "=r"(r[0]), "=r"(r[1]), "=r"(r[2]), "=r"(r[3]) : "r"(a));
}
__device__ __forceinline__ void mma16816(float (&d)[4], const uint32_t (&a)[4],
                                         uint32_t b0, uint32_t b1) {
    asm volatile(
        "mma.sync.aligned.m16n8k16.row.col.f32.bf16.bf16.f32 "
        "{%0,%1,%2,%3}, {%4,%5,%6,%7}, {%8,%9}, {%0,%1,%2,%3};"
        : "+f"(d[0]), "+f"(d[1]), "+f"(d[2]), "+f"(d[3])
        : "r"(a[0]), "r"(a[1]), "r"(a[2]), "r"(a[3]), "r"(b0), "r"(b1));
}
__device__ __forceinline__ void cpa16(void* dst, const void* src) {
    asm volatile("cp.async.cg.shared.global [%0], [%1], 16;"
                 :: "r"(saddr(dst)), "l"(src));
}
__device__ __forceinline__ void cpa16s(uint32_t dst, const void* src) {
    asm volatile("cp.async.cg.shared.global [%0], [%1], 16;"
                 :: "r"(dst), "l"(src));
}
__device__ __forceinline__ void cpa_commit() { asm volatile("cp.async.commit_group;"); }
__device__ __forceinline__ void cpa_wait0()  { asm volatile("cp.async.wait_group 0;"); }
__device__ __forceinline__ void cpa_wait1()  { asm volatile("cp.async.wait_group 1;"); }

__device__ __forceinline__ void fsplit(float x, unsigned short& h, unsigned short& l) {
    __nv_bfloat16 hb = __float2bfloat16_rn(x);
    __nv_bfloat16 lb = __float2bfloat16_rn(x - __bfloat162float(hb));
    h = __bfloat16_as_ushort(hb);
    l = __bfloat16_as_ushort(lb);
}

// ---------------------------------------------------------------------------
// cos/sin table
// ---------------------------------------------------------------------------
__global__ void build_cs(float2* cs) {
    const int idx = blockIdx.x * 256 + threadIdx.x;
    const int t = idx >> 5;
    const int i = idx & 31;
    const float inv_freq = powf(10000.0f, -(float)i * (1.0f / 32.0f));
    float c, s;
    sincosf((float)t * inv_freq, &s, &c);
    cs[idx] = make_float2(c, s);
}

// ---------------------------------------------------------------------------
// splits
// ---------------------------------------------------------------------------
__global__ void split_f32(const float* __restrict__ in,
                          __nv_bfloat16* __restrict__ hi,
                          __nv_bfloat16* __restrict__ lo) {
    const size_t i = ((size_t)blockIdx.x * 256 + threadIdx.x) * 4;
    float4 v = *(const float4*)(in + i);
    float f[4] = {v.x, v.y, v.z, v.w};
    unsigned short h[4], l[4];
#pragma unroll
    for (int e = 0; e < 4; e++) fsplit(f[e], h[e], l[e]);
    *(uint2*)(hi + i) = make_uint2((uint32_t)h[1] << 16 | h[0],
                                   (uint32_t)h[3] << 16 | h[2]);
    *(uint2*)(lo + i) = make_uint2((uint32_t)l[1] << 16 | l[0],
                                   (uint32_t)l[3] << 16 | l[2]);
}

__global__ void split_w6(const float* __restrict__ w0, const float* __restrict__ w1,
                         const float* __restrict__ w2, const float* __restrict__ w3,
                         const float* __restrict__ w4, const float* __restrict__ w5,
                         __nv_bfloat16* __restrict__ hi, __nv_bfloat16* __restrict__ lo) {
    const float* src[6] = {w0, w1, w2, w3, w4, w5};
    const float* in = src[blockIdx.y];
    const size_t off = (size_t)blockIdx.y * DD * DD;
    const size_t i = ((size_t)blockIdx.x * 256 + threadIdx.x) * 4;
    float4 v = *(const float4*)(in + i);
    float f[4] = {v.x, v.y, v.z, v.w};
    unsigned short h[4], l[4];
#pragma unroll
    for (int e = 0; e < 4; e++) fsplit(f[e], h[e], l[e]);
    *(uint2*)(hi + off + i) = make_uint2((uint32_t)h[1] << 16 | h[0],
                                         (uint32_t)h[3] << 16 | h[2]);
    *(uint2*)(lo + off + i) = make_uint2((uint32_t)l[1] << 16 | l[0],
                                         (uint32_t)l[3] << 16 | l[2]);
}

// ---------------------------------------------------------------------------
// 3-stage SW64-swizzled mainloop, k-chunk 32, prefetch distance 2.
// byte addressing: stage s at sb + (s%3)*GSTAGE_B; tiles Ah,Al,Wh,Wl.
// swizzle: 16B-chunk index ^= (row>>1)&3  (== off ^ ((off>>3)&0x30))
// ---------------------------------------------------------------------------
#define GEMM_MAINLOOP(Ah, Al, Wh, Wl, acc, sg, tid, m0, n0, wm, wn, lane)      \
    const uint32_t sb_ = saddr(sg);                                            \
    auto load_chunk = [&](int c) {                                             \
        const uint32_t base = sb_ + (uint32_t)(c % NSTG) * GSTAGE_B;           \
        const int k0 = c * 32;                                                 \
        _Pragma("unroll 2")                                                    \
        for (int i = tid; i < 512; i += 256) {                                 \
            const int r  = i >> 2;                                             \
            const int cb = (i & 3) * 16;            /* chunk byte 0..48 */     \
            const uint32_t sw = (uint32_t)(((r >> 1) & 3) << 4);               \
            const uint32_t so = (uint32_t)(r * 64) + ((uint32_t)cb ^ sw);      \
            const int ck = (i & 3) * 8;                                        \
            cpa16s(base + 0 * GTILE_B + so, Ah + (size_t)(m0 + r) * DD + k0 + ck);\
            cpa16s(base + 1 * GTILE_B + so, Al + (size_t)(m0 + r) * DD + k0 + ck);\
            cpa16s(base + 2 * GTILE_B + so, Wh + (size_t)(n0 + r) * DD + k0 + ck);\
            cpa16s(base + 3 * GTILE_B + so, Wl + (size_t)(n0 + r) * DD + k0 + ck);\
        }                                                                      \
        cpa_commit();                                                          \
    };                                                                         \
    load_chunk(0);                                                             \
    load_chunk(1);                                                             \
    for (int ch = 0; ch < NCH; ch++) {                                         \
        if (ch + 1 < NCH) cpa_wait1();                                         \
        else              cpa_wait0();                                         \
        __syncthreads();                                                       \
        if (ch + 2 < NCH) load_chunk(ch + 2);                                  \
        const uint32_t cur = sb_ + (uint32_t)(ch % NSTG) * GSTAGE_B;           \
        const int ar = wm * 64 + (lane & 15);                                  \
        const uint32_t swA = (uint32_t)(((ar >> 1) & 3) << 4);                 \
        const int br = wn * 32 + ((lane >> 4) & 1) * 8 + (lane & 7);           \
        const uint32_t swB = (uint32_t)(((br >> 1) & 3) << 4);                 \
        _Pragma("unroll")                                                      \
        for (int kk = 0; kk < 2; kk++) {                                       \
            uint32_t ahi[4][4], alo[4][4], bhi[2][4], blo[2][4];               \
            const uint32_t akb = ((uint32_t)(kk * 16 + (lane >> 4) * 8) * 2) ^ swA;\
            _Pragma("unroll")                                                  \
            for (int mi = 0; mi < 4; mi++) {                                   \
                const uint32_t ro = (uint32_t)((ar + mi * 16) * 64) + akb;     \
                ldmat_x4(ahi[mi], cur + 0 * GTILE_B + ro);                     \
                ldmat_x4(alo[mi], cur + 1 * GTILE_B + ro);                     \
            }                                                                  \
            const uint32_t bkb = ((uint32_t)(kk * 16 + ((lane >> 3) & 1) * 8) * 2) ^ swB;\
            _Pragma("unroll")                                                  \
            for (int p = 0; p < 2; p++) {                                      \
                const uint32_t ro = (uint32_t)((br + p * 16) * 64) + bkb;      \
                ldmat_x4(bhi[p], cur + 2 * GTILE_B + ro);                      \
                ldmat_x4(blo[p], cur + 3 * GTILE_B + ro);                      \
            }                                                                  \
            _Pragma("unroll")                                                  \
            for (int mi = 0; mi < 4; mi++)                                     \
                _Pragma("unroll")                                              \
                for (int ni = 0; ni < 4; ni++) {                               \
                    const uint32_t* bh = &bhi[ni >> 1][(ni & 1) * 2];          \
                    mma16816(acc[mi][ni], ahi[mi], bh[0], bh[1]);              \
                }                                                              \
            _Pragma("unroll")                                                  \
            for (int mi = 0; mi < 4; mi++)                                     \
                _Pragma("unroll")                                              \
                for (int ni = 0; ni < 4; ni++) {                               \
                    const uint32_t* bl = &blo[ni >> 1][(ni & 1) * 2];          \
                    mma16816(acc[mi][ni], ahi[mi], bl[0], bl[1]);              \
                }                                                              \
            _Pragma("unroll")                                                  \
            for (int mi = 0; mi < 4; mi++)                                     \
                _Pragma("unroll")                                              \
                for (int ni = 0; ni < 4; ni++) {                               \
                    const uint32_t* bh = &bhi[ni >> 1][(ni & 1) * 2];          \
                    mma16816(acc[mi][ni], alo[mi], bh[0], bh[1]);              \
                }                                                              \
        }                                                                      \
    }

// NOTE: the B-fragment rows within an 8-lane ldmatrix phase are br..br+7
// (consecutive), and A rows ar..ar+15 in two 8-row phases — the SW64 mapping
// gives each phase 8 distinct 16B segments (verified mod-128 walk), so all
// ldmatrix issues stay conflict-free.

// ---------------------------------------------------------------------------
// out-projection: plain fp32 epilogue
// ---------------------------------------------------------------------------
__global__ void __launch_bounds__(256, 2) gemm_plain(
        const __nv_bfloat16* __restrict__ Ah, const __nv_bfloat16* __restrict__ Al,
        const __nv_bfloat16* __restrict__ Wh, const __nv_bfloat16* __restrict__ Wl,
        float* __restrict__ C) {
    extern __shared__ __nv_bfloat16 sg[];
    const int tid  = threadIdx.x;
    const int wid  = tid >> 5;
    const int lane = tid & 31;
    const int m0 = blockIdx.y * 128;
    const int n0 = blockIdx.x * 128;
    const int wm = wid & 1;
    const int wn = wid >> 1;

    float acc[4][4][4];
#pragma unroll
    for (int i = 0; i < 4; i++)
#pragma unroll
        for (int j = 0; j < 4; j++)
#pragma unroll
            for (int c = 0; c < 4; c++) acc[i][j][c] = 0.0f;

    GEMM_MAINLOOP(Ah, Al, Wh, Wl, acc, sg, tid, m0, n0, wm, wn, lane)

#pragma unroll
    for (int mi = 0; mi < 4; mi++)
#pragma unroll
        for (int ni = 0; ni < 4; ni++) {
            const int r0 = m0 + wm * 64 + mi * 16 + (lane >> 2);
            const int c0 = n0 + wn * 32 + ni * 8 + (lane & 3) * 2;
            *(float2*)(C + (size_t)r0 * 1024 + c0) =
                make_float2(acc[mi][ni][0], acc[mi][ni][1]);
            *(float2*)(C + (size_t)(r0 + 8) * 1024 + c0) =
                make_float2(acc[mi][ni][2], acc[mi][ni][3]);
        }
}

// ---------------------------------------------------------------------------
// projections: fused vectorized RoPE + hi/lo split epilogue
// ---------------------------------------------------------------------------
__global__ void __launch_bounds__(256, 2) gemm_rope(
        const __nv_bfloat16* __restrict__ Ah, const __nv_bfloat16* __restrict__ Al,
        const __nv_bfloat16* __restrict__ Wh, const __nv_bfloat16* __restrict__ Wl,
        Outs outs, const float2* __restrict__ cs) {
    extern __shared__ __nv_bfloat16 sg[];
    const int zi = blockIdx.z;
    Wh += (size_t)zi * DD * DD;
    Wl += (size_t)zi * DD * DD;

    const int tid  = threadIdx.x;
    const int wid  = tid >> 5;
    const int lane = tid & 31;
    const int m0 = blockIdx.y * 128;
    const int n0 = blockIdx.x * 128;
    const int wm = wid & 1;
    const int wn = wid >> 1;

    float acc[4][4][4];
#pragma unroll
    for (int i = 0; i < 4; i++)
#pragma unroll
        for (int j = 0; j < 4; j++)
#pragma unroll
            for (int c = 0; c < 4; c++) acc[i][j][c] = 0.0f;

    GEMM_MAINLOOP(Ah, Al, Wh, Wl, acc, sg, tid, m0, n0, wm, wn, lane)

    // stage fp32 accumulators (67.6 KB <= 96 KB smem region)
    float* Sf = (float*)sg;
    __syncthreads();
#pragma unroll
    for (int mi = 0; mi < 4; mi++)
#pragma unroll
        for (int ni = 0; ni < 4; ni++) {
            const int rl = wm * 64 + mi * 16 + (lane >> 2);
            const int c0 = wn * 32 + ni * 8 + (lane & 3) * 2;
            *(float2*)(Sf + rl * FST + c0) =
                make_float2(acc[mi][ni][0], acc[mi][ni][1]);
            *(float2*)(Sf + (rl + 8) * FST + c0) =
                make_float2(acc[mi][ni][2], acc[mi][ni][3]);
        }
    __syncthreads();

    __nv_bfloat16* Oh = outs.hi[zi];
    __nv_bfloat16* Ol = outs.lo[zi];
    const bool dorope = (zi != 4);
    for (int it = tid; it < 2048; it += 256) {
        const int r  = it >> 4;
        const int c8 = (it & 15) * 8;
        float xt[8];
        *(float4*)(xt)     = *(const float4*)(Sf + r * FST + c8);
        *(float4*)(xt + 4) = *(const float4*)(Sf + r * FST + c8 + 4);
        float y[8];
        if (dorope) {
            const bool first = (c8 & 32) == 0;
            const int po = first ? 32 : -32;
            float xp[8];
            *(float4*)(xp)     = *(const float4*)(Sf + r * FST + c8 + po);
            *(float4*)(xp + 4) = *(const float4*)(Sf + r * FST + c8 + po + 4);
            const int t  = (m0 + r) & (TT - 1);
            const int ib = c8 & 31;
#pragma unroll
            for (int j = 0; j < 8; j++) {
                const float2 cc = cs[t * 32 + ib + j];
                y[j] = first ? fmaf(xt[j], cc.x, xp[j] * cc.y)
                             : fmaf(-xp[j], cc.y, xt[j] * cc.x);
            }
        } else {
#pragma unroll
            for (int j = 0; j < 8; j++) y[j] = xt[j];
        }
        unsigned short h[8], l[8];
#pragma unroll
        for (int j = 0; j < 8; j++) fsplit(y[j], h[j], l[j]);
        const uint4 hv = make_uint4((uint32_t)h[1] << 16 | h[0],
                                    (uint32_t)h[3] << 16 | h[2],
                                    (uint32_t)h[5] << 16 | h[4],
                                    (uint32_t)h[7] << 16 | h[6]);
        const uint4 lv = make_uint4((uint32_t)l[1] << 16 | l[0],
                                    (uint32_t)l[3] << 16 | l[2],
                                    (uint32_t)l[5] << 16 | l[4],
                                    (uint32_t)l[7] << 16 | l[6]);
        const size_t go = (size_t)(m0 + r) * DD + n0 + c8;
        *(uint4*)(Oh + go) = hv;
        *(uint4*)(Ol + go) = lv;
    }
}

// ---------------------------------------------------------------------------
// Tensor-core causal bilinear attention (unchanged from round 10).
// ---------------------------------------------------------------------------
__global__ void __launch_bounds__(256, 1) attn_mma(
        const __nv_bfloat16* __restrict__ qh,  const __nv_bfloat16* __restrict__ ql,
        const __nv_bfloat16* __restrict__ q2h, const __nv_bfloat16* __restrict__ q2l,
        const __nv_bfloat16* __restrict__ kh,  const __nv_bfloat16* __restrict__ kl,
        const __nv_bfloat16* __restrict__ k2h, const __nv_bfloat16* __restrict__ k2l,
        const __nv_bfloat16* __restrict__ vh,  const __nv_bfloat16* __restrict__ vl,
        __nv_bfloat16* __restrict__ zh, __nv_bfloat16* __restrict__ zl) {
    extern __shared__ __nv_bfloat16 sb2[];
    const int tid  = threadIdx.x;
    const int lane = tid & 31;
    const int w    = tid >> 5;
    const int qb = (int)gridDim.x - 1 - (int)blockIdx.x;
    const int q0 = qb * 128;
    const int b  = blockIdx.y >> 4;
    const int h  = blockIdx.y & 15;
    const size_t bh_off = (size_t)b * TT * DD + h * DH;

    {
        const __nv_bfloat16* src[4] = {qh, ql, q2h, q2l};
#pragma unroll
        for (int a = 0; a < 4; a++) {
            __nv_bfloat16* dst = sb2 + a * 128 * KST;
            for (int i = tid; i < 1024; i += 256) {
                const int r = i >> 3, ck = (i & 7) * 8;
                cpa16(dst + r * KST + ck, src[a] + bh_off + (size_t)(q0 + r) * DD + ck);
            }
        }
        cpa_commit();
        cpa_wait0();
        __syncthreads();
    }

    uint32_t fqh[4][4], fql[4][4], fq2h[4][4], fq2l[4][4];
    {
        const int ar = w * 16 + (lane & 15);
        const int ak = (lane >> 4) * 8;
#pragma unroll
        for (int kf = 0; kf < 4; kf++) {
            ldmat_x4(fqh [kf], saddr(sb2 + 0 * 128 * KST + ar * KST + kf * 16 + ak));
            ldmat_x4(fql [kf], saddr(sb2 + 1 * 128 * KST + ar * KST + kf * 16 + ak));
            ldmat_x4(fq2h[kf], saddr(sb2 + 2 * 128 * KST + ar * KST + kf * 16 + ak));
            ldmat_x4(fq2l[kf], saddr(sb2 + 3 * 128 * KST + ar * KST + kf * 16 + ak));
        }
    }
    __syncthreads();

    float zacc[8][4];
#pragma unroll
    for (int i = 0; i < 8; i++)
#pragma unroll
        for (int j = 0; j < 4; j++) zacc[i][j] = 0.0f;

    const int nkv = 2 * qb + 2;
    const int br = (lane & 7) + ((lane >> 4) & 1) * 8;
    const int bk = ((lane >> 3) & 1) * 8;
    const float invd2 = 1.0f / ((float)DH * (float)DH);

    auto load_tile = [&](int kj, int buf) {
        __nv_bfloat16* base = sb2 + buf * STAGE;
        const int kv0 = kj * 64;
        const __nv_bfloat16* src[6] = {kh, kl, k2h, k2l, vh, vl};
#pragma unroll
        for (int a = 0; a < 6; a++) {
            __nv_bfloat16* dst = base + a * ATILE;
            for (int i = tid; i < 512; i += 256) {
                const int r = i >> 3, ck = (i & 7) * 8;
                cpa16(dst + r * KST + ck, src[a] + bh_off + (size_t)(kv0 + r) * DD + ck);
            }
        }
    };

    load_tile(0, 0);
    cpa_commit();

    for (int kj = 0; kj < nkv; kj++) {
        cpa_wait0();
        __syncthreads();
        if (kj + 1 < nkv) {
            load_tile(kj + 1, (kj + 1) & 1);
            cpa_commit();
        }

        const __nv_bfloat16* base = sb2 + (kj & 1) * STAGE;
        const int kv0 = kj * 64;
        const bool masked = (kv0 >= q0);

        uint32_t ph[8][2], pl[8][2];
#pragma unroll
        for (int g = 0; g < 4; g++) {
            float s1f[2][4], s2f[2][4];
#pragma unroll
            for (int p = 0; p < 2; p++)
#pragma unroll
                for (int e = 0; e < 4; e++) { s1f[p][e] = 0.0f; s2f[p][e] = 0.0f; }

#pragma unroll
            for (int kf = 0; kf < 4; kf++) {
                uint32_t kh_[4], kl_[4], k2h_[4], k2l_[4];
                const int off = (g * 16 + br) * KST + kf * 16 + bk;
                ldmat_x4(kh_,  saddr(base + 0 * ATILE + off));
                ldmat_x4(kl_,  saddr(base + 1 * ATILE + off));
                ldmat_x4(k2h_, saddr(base + 2 * ATILE + off));
                ldmat_x4(k2l_, saddr(base + 3 * ATILE + off));
#pragma unroll
                for (int p = 0; p < 2; p++) {
                    mma16816(s1f[p], fqh[kf],  kh_[p*2],  kh_[p*2+1]);
                    mma16816(s2f[p], fq2h[kf], k2h_[p*2], k2h_[p*2+1]);
                }
#pragma unroll
                for (int p = 0; p < 2; p++) {
                    mma16816(s1f[p], fqh[kf],  kl_[p*2],  kl_[p*2+1]);
                    mma16816(s2f[p], fq2h[kf], k2l_[p*2], k2l_[p*2+1]);
                }
#pragma unroll
                for (int p = 0; p < 2; p++) {
                    mma16816(s1f[p], fql[kf],  kh_[p*2],  kh_[p*2+1]);
                    mma16816(s2f[p], fq2l[kf], k2h_[p*2], k2h_[p*2+1]);
                }
            }
#pragma unroll
            for (int p = 0; p < 2; p++) {
                const int j = g * 2 + p;
                float pr[4];
#pragma unroll
                for (int e = 0; e < 4; e++) pr[e] = s1f[p][e] * s2f[p][e] * invd2;
                if (masked) {
                    const int qr = q0 + w * 16 + (lane >> 2);
                    const int kc = kv0 + j * 8 + (lane & 3) * 2;
                    if (kc     > qr)     pr[0] = 0.0f;
                    if (kc + 1 > qr)     pr[1] = 0.0f;
                    if (kc     > qr + 8) pr[2] = 0.0f;
                    if (kc + 1 > qr + 8) pr[3] = 0.0f;
                }
                unsigned short hh[4], ll[4];
#pragma unroll
                for (int e = 0; e < 4; e++) fsplit(pr[e], hh[e], ll[e]);
                ph[j][0] = (uint32_t)hh[1] << 16 | hh[0];
                ph[j][1] = (uint32_t)hh[3] << 16 | hh[2];
                pl[j][0] = (uint32_t)ll[1] << 16 | ll[0];
                pl[j][1] = (uint32_t)ll[3] << 16 | ll[2];
            }
        }

        const int vr_lane = ((lane >> 3) & 1) * 8 + (lane & 7);
        const int vc_lane = ((lane >> 4) & 1) * 8;
#pragma unroll
        for (int f = 0; f < 4; f++) {
            uint32_t ah[4] = {ph[2*f][0], ph[2*f][1], ph[2*f+1][0], ph[2*f+1][1]};
            uint32_t al[4] = {pl[2*f][0], pl[2*f][1], pl[2*f+1][0], pl[2*f+1][1]};
            uint32_t vh_[4][4], vl_[4][4];
#pragma unroll
            for (int gd = 0; gd < 4; gd++) {
                const int off = (f * 16 + vr_lane) * KST + gd * 16 + vc_lane;
                ldmat_x4_trans(vh_[gd], saddr(base + 4 * ATILE + off));
                ldmat_x4_trans(vl_[gd], saddr(base + 5 * ATILE + off));
            }
#pragma unroll
            for (int gd = 0; gd < 4; gd++)
#pragma unroll
                for (int p = 0; p < 2; p++)
                    mma16816(zacc[gd*2+p], ah, vh_[gd][p*2], vh_[gd][p*2+1]);
#pragma unroll
            for (int gd = 0; gd < 4; gd++)
#pragma unroll
                for (int p = 0; p < 2; p++)
                    mma16816(zacc[gd*2+p], ah, vl_[gd][p*2], vl_[gd][p*2+1]);
#pragma unroll
            for (int gd = 0; gd < 4; gd++)
#pragma unroll
                for (int p = 0; p < 2; p++)
                    mma16816(zacc[gd*2+p], al, vh_[gd][p*2], vh_[gd][p*2+1]);
        }
    }

    {
        const int r = q0 + w * 16 + (lane >> 2);
        const int c = (lane & 3) * 2;
#pragma unroll
        for (int nd = 0; nd < 8; nd++) {
            unsigned short h0, l0, h1, l1;
#pragma unroll
            for (int half = 0; half < 2; half++) {
                fsplit(zacc[nd][half * 2 + 0], h0, l0);
                fsplit(zacc[nd][half * 2 + 1], h1, l1);
                const size_t off = bh_off + (size_t)(r + half * 8) * DD + nd * 8 + c;
                *(uint32_t*)(zh + off) = (uint32_t)h1 << 16 | h0;
                *(uint32_t*)(zl + off) = (uint32_t)l1 << 16 | l0;
            }
        }
    }
}

// ---------------------------------------------------------------------------
extern "C" void kernel_launch(void* const* d_in, const int* in_sizes, int n_in,
                              void* d_out, int out_size) {
    const float* x     = (const float*)d_in[0];
    const float* Wq    = (const float*)d_in[1];
    const float* Wk    = (const float*)d_in[2];
    const float* Wq2   = (const float*)d_in[3];
    const float* Wk2   = (const float*)d_in[4];
    const float* Wv    = (const float*)d_in[5];
    const float* Wproj = (const float*)d_in[6];
    float* out = (float*)d_out;

    float2* cs;
    cudaGetSymbolAddress((void**)&cs, g_cs);

    __nv_bfloat16 *xh, *xl, *zh, *zl, *w6h, *w6l;
    cudaGetSymbolAddress((void**)&xh,  g_xh);  cudaGetSymbolAddress((void**)&xl,  g_xl);
    cudaGetSymbolAddress((void**)&zh,  g_zh);  cudaGetSymbolAddress((void**)&zl,  g_zl);
    cudaGetSymbolAddress((void**)&w6h, g_w6h); cudaGetSymbolAddress((void**)&w6l, g_w6l);

    __nv_bfloat16 *qh, *ql, *q2h, *q2l, *kh, *kl, *k2h, *k2l, *vh, *vl;
    cudaGetSymbolAddress((void**)&qh,  g_qh);  cudaGetSymbolAddress((void**)&ql,  g_ql);
    cudaGetSymbolAddress((void**)&q2h, g_q2h); cudaGetSymbolAddress((void**)&q2l, g_q2l);
    cudaGetSymbolAddress((void**)&kh,  g_kh);  cudaGetSymbolAddress((void**)&kl,  g_kl);
    cudaGetSymbolAddress((void**)&k2h, g_k2h); cudaGetSymbolAddress((void**)&k2l, g_k2l);
    cudaGetSymbolAddress((void**)&vh,  g_vh);  cudaGetSymbolAddress((void**)&vl,  g_vl);

    Outs outs;
    outs.hi[0] = qh;  outs.lo[0] = ql;
    outs.hi[1] = kh;  outs.lo[1] = kl;
    outs.hi[2] = q2h; outs.lo[2] = q2l;
    outs.hi[3] = k2h; outs.lo[3] = k2l;
    outs.hi[4] = vh;  outs.lo[4] = vl;

    cudaFuncSetAttribute(gemm_plain,
                         cudaFuncAttributeMaxDynamicSharedMemorySize, GEMM_SMEM);
    cudaFuncSetAttribute(gemm_rope,
                         cudaFuncAttributeMaxDynamicSharedMemorySize, GEMM_SMEM);

    // 0) cos/sin table
    build_cs<<<TT * 32 / 256, 256>>>(cs);

    // 1) split inputs
    split_f32<<<MM * DD / 1024, 256>>>(x, xh, xl);
    split_w6<<<dim3(DD * DD / 1024, 6), 256>>>(Wq, Wk, Wq2, Wk2, Wv, Wproj, w6h, w6l);

    // 2) five fused projections, 3-stage pipeline, 2 CTAs/SM
    gemm_rope<<<dim3(DD / 128, MM / 128, 5), 256, GEMM_SMEM>>>(
        xh, xl, w6h, w6l, outs, cs);

    // 3) attention (writes zh/zl directly)
    const int attn_smem = 2 * STAGE * (int)sizeof(__nv_bfloat16);
    cudaFuncSetAttribute(attn_mma,
                         cudaFuncAttributeMaxDynamicSharedMemorySize, attn_smem);
    attn_mma<<<dim3(TT / 128, BB * HH), 256, attn_smem>>>(
        qh, ql, q2h, q2l, kh, kl, k2h, k2l, vh, vl, zh, zl);

    // 4) output projection, 3-stage pipeline, 2 CTAs/SM
    gemm_plain<<<dim3(DD / 128, MM / 128, 1), 256, GEMM_SMEM>>>(
        zh, zl, w6h + (size_t)5 * DD * DD, w6l + (size_t)5 * DD * DD, out);
}

// round 16
// speedup vs baseline: 1.2598x; 1.0100x over previous
#include <cuda_runtime.h>
#include <cuda_bf16.h>
#include <math.h>
#include <stdint.h>

#define BB 2
#define TT 2048
#define DD 1024
#define HH 16
#define DH 64
#define MM (BB*TT)

/* ---- gemm geometry: CTA 128x128, 8 warps (64x32), k-chunk 32,
       SW64-swizzled 64B rows, 3 stages, 96KB smem -> 2 CTAs/SM ---- */
#define GTILE_B 8192u
#define GSTAGE_B (4u*GTILE_B)
#define NSTG 3
#define NCH  32
#define GEMM_SMEM (NSTG*GSTAGE_B)   /* 98304 B */
#define FST 132

/* ---- attn geometry: SW128 128B rows, 3 stages, prefetch distance 2 ---- */
#define ATILE_B 8192u               /* 64 rows x 128 B */
#define ASTAGE_B (6u*ATILE_B)       /* 49152 B */
#define ANSTG 3
#define ATTN_SMEM (ANSTG*ASTAGE_B)  /* 147456 B */
#define QTILE_B 16384u              /* 128 rows x 128 B */
#define ASWZ(r, cb) ((uint32_t)(cb) ^ (uint32_t)((((r) & 7)) << 4))

// ---------------- scratch (device globals) ----------------------------------
__device__ float2 g_cs[TT*32];
__device__ __nv_bfloat16 g_xh [MM*DD], g_xl [MM*DD];
__device__ __nv_bfloat16 g_zh [MM*DD], g_zl [MM*DD];
__device__ __nv_bfloat16 g_w6h[6*DD*DD], g_w6l[6*DD*DD];
__device__ __nv_bfloat16 g_qh [MM*DD], g_ql [MM*DD];
__device__ __nv_bfloat16 g_q2h[MM*DD], g_q2l[MM*DD];
__device__ __nv_bfloat16 g_kh [MM*DD], g_kl [MM*DD];
__device__ __nv_bfloat16 g_k2h[MM*DD], g_k2l[MM*DD];
__device__ __nv_bfloat16 g_vh [MM*DD], g_vl [MM*DD];

struct Outs { __nv_bfloat16* hi[5]; __nv_bfloat16* lo[5]; };

// ---------------------------------------------------------------------------
__device__ __forceinline__ uint32_t saddr(const void* p) {
    return (uint32_t)__cvta_generic_to_shared(p);
}
__device__ __forceinline__ void ldmat_x4(uint32_t (&r)[4], uint32_t a) {
    asm volatile("ldmatrix.sync.aligned.m8n8.x4.shared.b16 {%0,%1,%2,%3}, [%4];"
                 : "=r"(r[0]), "=r"(r[1]), "=r"(r[2]), "=r"(r[3]) : "r"(a));
}
__device__ __forceinline__ void ldmat_x4_trans(uint32_t (&r)[4], uint32_t a) {
    asm volatile("ldmatrix.sync.aligned.m8n8.x4.trans.shared.b16 {%0,%1,%2,%3}, [%4];"
                 : "=r"(r[0]), "=r"(r[1]), "=r"(r[2]), "=r"(r[3]) : "r"(a));
}
__device__ __forceinline__ void mma16816(float (&d)[4], const uint32_t (&a)[4],
                                         uint32_t b0, uint32_t b1) {
    asm volatile(
        "mma.sync.aligned.m16n8k16.row.col.f32.bf16.bf16.f32 "
        "{%0,%1,%2,%3}, {%4,%5,%6,%7}, {%8,%9}, {%0,%1,%2,%3};"
        : "+f"(d[0]), "+f"(d[1]), "+f"(d[2]), "+f"(d[3])
        : "r"(a[0]), "r"(a[1]), "r"(a[2]), "r"(a[3]), "r"(b0), "r"(b1));
}
__device__ __forceinline__ void cpa16s(uint32_t dst, const void* src) {
    asm volatile("cp.async.cg.shared.global [%0], [%1], 16;"
                 :: "r"(dst), "l"(src));
}
__device__ __forceinline__ void cpa_commit() { asm volatile("cp.async.commit_group;"); }
__device__ __forceinline__ void cpa_wait0()  { asm volatile("cp.async.wait_group 0;"); }
__device__ __forceinline__ void cpa_wait1()  { asm volatile("cp.async.wait_group 1;"); }

__device__ __forceinline__ void fsplit(float x, unsigned short& h, unsigned short& l) {
    __nv_bfloat16 hb = __float2bfloat16_rn(x);
    __nv_bfloat16 lb = __float2bfloat16_rn(x - __bfloat162float(hb));
    h = __bfloat16_as_ushort(hb);
    l = __bfloat16_as_ushort(lb);
}

// ---------------------------------------------------------------------------
// cos/sin table
// ---------------------------------------------------------------------------
__global__ void build_cs(float2* cs) {
    const int idx = blockIdx.x * 256 + threadIdx.x;
    const int t = idx >> 5;
    const int i = idx & 31;
    const float inv_freq = powf(10000.0f, -(float)i * (1.0f / 32.0f));
    float c, s;
    sincosf((float)t * inv_freq, &s, &c);
    cs[idx] = make_float2(c, s);
}

// ---------------------------------------------------------------------------
// splits
// ---------------------------------------------------------------------------
__global__ void split_f32(const float* __restrict__ in,
                          __nv_bfloat16* __restrict__ hi,
                          __nv_bfloat16* __restrict__ lo) {
    const size_t i = ((size_t)blockIdx.x * 256 + threadIdx.x) * 4;
    float4 v = *(const float4*)(in + i);
    float f[4] = {v.x, v.y, v.z, v.w};
    unsigned short h[4], l[4];
#pragma unroll
    for (int e = 0; e < 4; e++) fsplit(f[e], h[e], l[e]);
    *(uint2*)(hi + i) = make_uint2((uint32_t)h[1] << 16 | h[0],
                                   (uint32_t)h[3] << 16 | h[2]);
    *(uint2*)(lo + i) = make_uint2((uint32_t)l[1] << 16 | l[0],
                                   (uint32_t)l[3] << 16 | l[2]);
}

__global__ void split_w6(const float* __restrict__ w0, const float* __restrict__ w1,
                         const float* __restrict__ w2, const float* __restrict__ w3,
                         const float* __restrict__ w4, const float* __restrict__ w5,
                         __nv_bfloat16* __restrict__ hi, __nv_bfloat16* __restrict__ lo) {
    const float* src[6] = {w0, w1, w2, w3, w4, w5};
    const float* in = src[blockIdx.y];
    const size_t off = (size_t)blockIdx.y * DD * DD;
    const size_t i = ((size_t)blockIdx.x * 256 + threadIdx.x) * 4;
    float4 v = *(const float4*)(in + i);
    float f[4] = {v.x, v.y, v.z, v.w};
    unsigned short h[4], l[4];
#pragma unroll
    for (int e = 0; e < 4; e++) fsplit(f[e], h[e], l[e]);
    *(uint2*)(hi + off + i) = make_uint2((uint32_t)h[1] << 16 | h[0],
                                         (uint32_t)h[3] << 16 | h[2]);
    *(uint2*)(lo + off + i) = make_uint2((uint32_t)l[1] << 16 | l[0],
                                         (uint32_t)l[3] << 16 | l[2]);
}

// ---------------------------------------------------------------------------
// 3-stage SW64-swizzled gemm mainloop (round 15, unchanged)
// ---------------------------------------------------------------------------
#define GEMM_MAINLOOP(Ah, Al, Wh, Wl, acc, sg, tid, m0, n0, wm, wn, lane)      \
    const uint32_t sb_ = saddr(sg);                                            \
    auto load_chunk = [&](int c) {                                             \
        const uint32_t base = sb_ + (uint32_t)(c % NSTG) * GSTAGE_B;           \
        const int k0 = c * 32;                                                 \
        _Pragma("unroll 2")                                                    \
        for (int i = tid; i < 512; i += 256) {                                 \
            const int r  = i >> 2;                                             \
            const int cb = (i & 3) * 16;                                       \
            const uint32_t sw = (uint32_t)(((r >> 1) & 3) << 4);               \
            const uint32_t so = (uint32_t)(r * 64) + ((uint32_t)cb ^ sw);      \
            const int ck = (i & 3) * 8;                                        \
            cpa16s(base + 0 * GTILE_B + so, Ah + (size_t)(m0 + r) * DD + k0 + ck);\
            cpa16s(base + 1 * GTILE_B + so, Al + (size_t)(m0 + r) * DD + k0 + ck);\
            cpa16s(base + 2 * GTILE_B + so, Wh + (size_t)(n0 + r) * DD + k0 + ck);\
            cpa16s(base + 3 * GTILE_B + so, Wl + (size_t)(n0 + r) * DD + k0 + ck);\
        }                                                                      \
        cpa_commit();                                                          \
    };                                                                         \
    load_chunk(0);                                                             \
    load_chunk(1);                                                             \
    for (int ch = 0; ch < NCH; ch++) {                                         \
        if (ch + 1 < NCH) cpa_wait1();                                         \
        else              cpa_wait0();                                         \
        __syncthreads();                                                       \
        if (ch + 2 < NCH) load_chunk(ch + 2);                                  \
        const uint32_t cur = sb_ + (uint32_t)(ch % NSTG) * GSTAGE_B;           \
        const int ar = wm * 64 + (lane & 15);                                  \
        const uint32_t swA = (uint32_t)(((ar >> 1) & 3) << 4);                 \
        const int br = wn * 32 + ((lane >> 4) & 1) * 8 + (lane & 7);           \
        const uint32_t swB = (uint32_t)(((br >> 1) & 3) << 4);                 \
        _Pragma("unroll")                                                      \
        for (int kk = 0; kk < 2; kk++) {                                       \
            uint32_t ahi[4][4], alo[4][4], bhi[2][4], blo[2][4];               \
            const uint32_t akb = ((uint32_t)(kk * 16 + (lane >> 4) * 8) * 2) ^ swA;\
            _Pragma("unroll")                                                  \
            for (int mi = 0; mi < 4; mi++) {                                   \
                const uint32_t ro = (uint32_t)((ar + mi * 16) * 64) + akb;     \
                ldmat_x4(ahi[mi], cur + 0 * GTILE_B + ro);                     \
                ldmat_x4(alo[mi], cur + 1 * GTILE_B + ro);                     \
            }                                                                  \
            const uint32_t bkb = ((uint32_t)(kk * 16 + ((lane >> 3) & 1) * 8) * 2) ^ swB;\
            _Pragma("unroll")                                                  \
            for (int p = 0; p < 2; p++) {                                      \
                const uint32_t ro = (uint32_t)((br + p * 16) * 64) + bkb;      \
                ldmat_x4(bhi[p], cur + 2 * GTILE_B + ro);                      \
                ldmat_x4(blo[p], cur + 3 * GTILE_B + ro);                      \
            }                                                                  \
            _Pragma("unroll")                                                  \
            for (int mi = 0; mi < 4; mi++)                                     \
                _Pragma("unroll")                                              \
                for (int ni = 0; ni < 4; ni++) {                               \
                    const uint32_t* bh = &bhi[ni >> 1][(ni & 1) * 2];          \
                    mma16816(acc[mi][ni], ahi[mi], bh[0], bh[1]);              \
                }                                                              \
            _Pragma("unroll")                                                  \
            for (int mi = 0; mi < 4; mi++)                                     \
                _Pragma("unroll")                                              \
                for (int ni = 0; ni < 4; ni++) {                               \
                    const uint32_t* bl = &blo[ni >> 1][(ni & 1) * 2];          \
                    mma16816(acc[mi][ni], ahi[mi], bl[0], bl[1]);              \
                }                                                              \
            _Pragma("unroll")                                                  \
            for (int mi = 0; mi < 4; mi++)                                     \
                _Pragma("unroll")                                              \
                for (int ni = 0; ni < 4; ni++) {                               \
                    const uint32_t* bh = &bhi[ni >> 1][(ni & 1) * 2];          \
                    mma16816(acc[mi][ni], alo[mi], bh[0], bh[1]);              \
                }                                                              \
        }                                                                      \
    }

// ---------------------------------------------------------------------------
// out-projection: plain fp32 epilogue
// ---------------------------------------------------------------------------
__global__ void __launch_bounds__(256, 2) gemm_plain(
        const __nv_bfloat16* __restrict__ Ah, const __nv_bfloat16* __restrict__ Al,
        const __nv_bfloat16* __restrict__ Wh, const __nv_bfloat16* __restrict__ Wl,
        float* __restrict__ C) {
    extern __shared__ __nv_bfloat16 sg[];
    const int tid  = threadIdx.x;
    const int wid  = tid >> 5;
    const int lane = tid & 31;
    const int m0 = blockIdx.y * 128;
    const int n0 = blockIdx.x * 128;
    const int wm = wid & 1;
    const int wn = wid >> 1;

    float acc[4][4][4];
#pragma unroll
    for (int i = 0; i < 4; i++)
#pragma unroll
        for (int j = 0; j < 4; j++)
#pragma unroll
            for (int c = 0; c < 4; c++) acc[i][j][c] = 0.0f;

    GEMM_MAINLOOP(Ah, Al, Wh, Wl, acc, sg, tid, m0, n0, wm, wn, lane)

#pragma unroll
    for (int mi = 0; mi < 4; mi++)
#pragma unroll
        for (int ni = 0; ni < 4; ni++) {
            const int r0 = m0 + wm * 64 + mi * 16 + (lane >> 2);
            const int c0 = n0 + wn * 32 + ni * 8 + (lane & 3) * 2;
            *(float2*)(C + (size_t)r0 * 1024 + c0) =
                make_float2(acc[mi][ni][0], acc[mi][ni][1]);
            *(float2*)(C + (size_t)(r0 + 8) * 1024 + c0) =
                make_float2(acc[mi][ni][2], acc[mi][ni][3]);
        }
}

// ---------------------------------------------------------------------------
// projections: fused vectorized RoPE + hi/lo split epilogue
// ---------------------------------------------------------------------------
__global__ void __launch_bounds__(256, 2) gemm_rope(
        const __nv_bfloat16* __restrict__ Ah, const __nv_bfloat16* __restrict__ Al,
        const __nv_bfloat16* __restrict__ Wh, const __nv_bfloat16* __restrict__ Wl,
        Outs outs, const float2* __restrict__ cs) {
    extern __shared__ __nv_bfloat16 sg[];
    const int zi = blockIdx.z;
    Wh += (size_t)zi * DD * DD;
    Wl += (size_t)zi * DD * DD;

    const int tid  = threadIdx.x;
    const int wid  = tid >> 5;
    const int lane = tid & 31;
    const int m0 = blockIdx.y * 128;
    const int n0 = blockIdx.x * 128;
    const int wm = wid & 1;
    const int wn = wid >> 1;

    float acc[4][4][4];
#pragma unroll
    for (int i = 0; i < 4; i++)
#pragma unroll
        for (int j = 0; j < 4; j++)
#pragma unroll
            for (int c = 0; c < 4; c++) acc[i][j][c] = 0.0f;

    GEMM_MAINLOOP(Ah, Al, Wh, Wl, acc, sg, tid, m0, n0, wm, wn, lane)

    float* Sf = (float*)sg;
    __syncthreads();
#pragma unroll
    for (int mi = 0; mi < 4; mi++)
#pragma unroll
        for (int ni = 0; ni < 4; ni++) {
            const int rl = wm * 64 + mi * 16 + (lane >> 2);
            const int c0 = wn * 32 + ni * 8 + (lane & 3) * 2;
            *(float2*)(Sf + rl * FST + c0) =
                make_float2(acc[mi][ni][0], acc[mi][ni][1]);
            *(float2*)(Sf + (rl + 8) * FST + c0) =
                make_float2(acc[mi][ni][2], acc[mi][ni][3]);
        }
    __syncthreads();

    __nv_bfloat16* Oh = outs.hi[zi];
    __nv_bfloat16* Ol = outs.lo[zi];
    const bool dorope = (zi != 4);
    for (int it = tid; it < 2048; it += 256) {
        const int r  = it >> 4;
        const int c8 = (it & 15) * 8;
        float xt[8];
        *(float4*)(xt)     = *(const float4*)(Sf + r * FST + c8);
        *(float4*)(xt + 4) = *(const float4*)(Sf + r * FST + c8 + 4);
        float y[8];
        if (dorope) {
            const bool first = (c8 & 32) == 0;
            const int po = first ? 32 : -32;
            float xp[8];
            *(float4*)(xp)     = *(const float4*)(Sf + r * FST + c8 + po);
            *(float4*)(xp + 4) = *(const float4*)(Sf + r * FST + c8 + po + 4);
            const int t  = (m0 + r) & (TT - 1);
            const int ib = c8 & 31;
#pragma unroll
            for (int j = 0; j < 8; j++) {
                const float2 cc = cs[t * 32 + ib + j];
                y[j] = first ? fmaf(xt[j], cc.x, xp[j] * cc.y)
                             : fmaf(-xp[j], cc.y, xt[j] * cc.x);
            }
        } else {
#pragma unroll
            for (int j = 0; j < 8; j++) y[j] = xt[j];
        }
        unsigned short h[8], l[8];
#pragma unroll
        for (int j = 0; j < 8; j++) fsplit(y[j], h[j], l[j]);
        const uint4 hv = make_uint4((uint32_t)h[1] << 16 | h[0],
                                    (uint32_t)h[3] << 16 | h[2],
                                    (uint32_t)h[5] << 16 | h[4],
                                    (uint32_t)h[7] << 16 | h[6]);
        const uint4 lv = make_uint4((uint32_t)l[1] << 16 | l[0],
                                    (uint32_t)l[3] << 16 | l[2],
                                    (uint32_t)l[5] << 16 | l[4],
                                    (uint32_t)l[7] << 16 | l[6]);
        const size_t go = (size_t)(m0 + r) * DD + n0 + c8;
        *(uint4*)(Oh + go) = hv;
        *(uint4*)(Ol + go) = lv;
    }
}

// ---------------------------------------------------------------------------
// Tensor-core causal bilinear attention.
// SW128 unpadded tiles (128B rows), 3-stage ring, prefetch distance 2.
// ---------------------------------------------------------------------------
__global__ void __launch_bounds__(256, 1) attn_mma(
        const __nv_bfloat16* __restrict__ qh,  const __nv_bfloat16* __restrict__ ql,
        const __nv_bfloat16* __restrict__ q2h, const __nv_bfloat16* __restrict__ q2l,
        const __nv_bfloat16* __restrict__ kh,  const __nv_bfloat16* __restrict__ kl,
        const __nv_bfloat16* __restrict__ k2h, const __nv_bfloat16* __restrict__ k2l,
        const __nv_bfloat16* __restrict__ vh,  const __nv_bfloat16* __restrict__ vl,
        __nv_bfloat16* __restrict__ zh, __nv_bfloat16* __restrict__ zl) {
    extern __shared__ __nv_bfloat16 sb2[];
    const uint32_t ab = saddr(sb2);
    const int tid  = threadIdx.x;
    const int lane = tid & 31;
    const int w    = tid >> 5;
    const int qb = (int)gridDim.x - 1 - (int)blockIdx.x;
    const int q0 = qb * 128;
    const int b  = blockIdx.y >> 4;
    const int h  = blockIdx.y & 15;
    const size_t bh_off = (size_t)b * TT * DD + h * DH;

    // ---- stage Q tiles (SW128), load fragments, then free the space ----
    {
        const __nv_bfloat16* src[4] = {qh, ql, q2h, q2l};
#pragma unroll
        for (int a = 0; a < 4; a++) {
            for (int i = tid; i < 1024; i += 256) {
                const int r = i >> 3;
                const uint32_t cb = (uint32_t)(i & 7) * 16;
                cpa16s(ab + a * QTILE_B + (uint32_t)(r * 128) + ASWZ(r, cb),
                       src[a] + bh_off + (size_t)(q0 + r) * DD + (i & 7) * 8);
            }
        }
        cpa_commit();
        cpa_wait0();
        __syncthreads();
    }

    uint32_t fqh[4][4], fql[4][4], fq2h[4][4], fq2l[4][4];
    {
        const int ar = w * 16 + (lane & 15);
        const uint32_t akb = (uint32_t)(lane >> 4) * 16;   // 0 or 16 bytes
#pragma unroll
        for (int kf = 0; kf < 4; kf++) {
            const uint32_t ro = (uint32_t)(ar * 128) + ASWZ(ar, kf * 32 + akb);
            ldmat_x4(fqh [kf], ab + 0 * QTILE_B + ro);
            ldmat_x4(fql [kf], ab + 1 * QTILE_B + ro);
            ldmat_x4(fq2h[kf], ab + 2 * QTILE_B + ro);
            ldmat_x4(fq2l[kf], ab + 3 * QTILE_B + ro);
        }
    }
    __syncthreads();   // all frags read; smem free for K/V ring

    float zacc[8][4];
#pragma unroll
    for (int i = 0; i < 8; i++)
#pragma unroll
        for (int j = 0; j < 4; j++) zacc[i][j] = 0.0f;

    const int nkv = 2 * qb + 2;
    const int br = (lane & 7) + ((lane >> 4) & 1) * 8;
    const uint32_t bkB = (uint32_t)((lane >> 3) & 1) * 16;
    const float invd2 = 1.0f / ((float)DH * (float)DH);

    auto load_tile = [&](int kj) {
        const uint32_t base = ab + (uint32_t)(kj % ANSTG) * ASTAGE_B;
        const int kv0 = kj * 64;
        const __nv_bfloat16* src[6] = {kh, kl, k2h, k2l, vh, vl};
#pragma unroll
        for (int a = 0; a < 6; a++) {
            for (int i = tid; i < 512; i += 256) {
                const int r = i >> 3;
                const uint32_t cb = (uint32_t)(i & 7) * 16;
                cpa16s(base + a * ATILE_B + (uint32_t)(r * 128) + ASWZ(r, cb),
                       src[a] + bh_off + (size_t)(kv0 + r) * DD + (i & 7) * 8);
            }
        }
        cpa_commit();
    };

    load_tile(0);
    load_tile(1);

    for (int kj = 0; kj < nkv; kj++) {
        if (kj + 1 < nkv) cpa_wait1();
        else              cpa_wait0();
        __syncthreads();
        if (kj + 2 < nkv) load_tile(kj + 2);

        const uint32_t base = ab + (uint32_t)(kj % ANSTG) * ASTAGE_B;
        const int kv0 = kj * 64;
        const bool masked = (kv0 >= q0);

        uint32_t ph[8][2], pl[8][2];
#pragma unroll
        for (int g = 0; g < 4; g++) {
            float s1f[2][4], s2f[2][4];
#pragma unroll
            for (int p = 0; p < 2; p++)
#pragma unroll
                for (int e = 0; e < 4; e++) { s1f[p][e] = 0.0f; s2f[p][e] = 0.0f; }

            const int krow = g * 16 + br;
#pragma unroll
            for (int kf = 0; kf < 4; kf++) {
                uint32_t kh_[4], kl_[4], k2h_[4], k2l_[4];
                const uint32_t ro = (uint32_t)(krow * 128)
                                  + ASWZ(krow, kf * 32 + bkB);
                ldmat_x4(kh_,  base + 0 * ATILE_B + ro);
                ldmat_x4(kl_,  base + 1 * ATILE_B + ro);
                ldmat_x4(k2h_, base + 2 * ATILE_B + ro);
                ldmat_x4(k2l_, base + 3 * ATILE_B + ro);
#pragma unroll
                for (int p = 0; p < 2; p++) {
                    mma16816(s1f[p], fqh[kf],  kh_[p*2],  kh_[p*2+1]);
                    mma16816(s2f[p], fq2h[kf], k2h_[p*2], k2h_[p*2+1]);
                }
#pragma unroll
                for (int p = 0; p < 2; p++) {
                    mma16816(s1f[p], fqh[kf],  kl_[p*2],  kl_[p*2+1]);
                    mma16816(s2f[p], fq2h[kf], k2l_[p*2], k2l_[p*2+1]);
                }
#pragma unroll
                for (int p = 0; p < 2; p++) {
                    mma16816(s1f[p], fql[kf],  kh_[p*2],  kh_[p*2+1]);
                    mma16816(s2f[p], fq2l[kf], k2h_[p*2], k2h_[p*2+1]);
                }
            }
#pragma unroll
            for (int p = 0; p < 2; p++) {
                const int j = g * 2 + p;
                float pr[4];
#pragma unroll
                for (int e = 0; e < 4; e++) pr[e] = s1f[p][e] * s2f[p][e] * invd2;
                if (masked) {
                    const int qr = q0 + w * 16 + (lane >> 2);
                    const int kc = kv0 + j * 8 + (lane & 3) * 2;
                    if (kc     > qr)     pr[0] = 0.0f;
                    if (kc + 1 > qr)     pr[1] = 0.0f;
                    if (kc     > qr + 8) pr[2] = 0.0f;
                    if (kc + 1 > qr + 8) pr[3] = 0.0f;
                }
                unsigned short hh[4], ll[4];
#pragma unroll
                for (int e = 0; e < 4; e++) fsplit(pr[e], hh[e], ll[e]);
                ph[j][0] = (uint32_t)hh[1] << 16 | hh[0];
                ph[j][1] = (uint32_t)hh[3] << 16 | hh[2];
                pl[j][0] = (uint32_t)ll[1] << 16 | ll[0];
                pl[j][1] = (uint32_t)ll[3] << 16 | ll[2];
            }
        }

        // PV: V fragments via ldmatrix.trans from natural [kv][d] SW128 tiles
        const int vr_lane = ((lane >> 3) & 1) * 8 + (lane & 7);
        const uint32_t vcB = (uint32_t)((lane >> 4) & 1) * 16;
#pragma unroll
        for (int f = 0; f < 4; f++) {
            uint32_t ah[4] = {ph[2*f][0], ph[2*f][1], ph[2*f+1][0], ph[2*f+1][1]};
            uint32_t al[4] = {pl[2*f][0], pl[2*f][1], pl[2*f+1][0], pl[2*f+1][1]};
            uint32_t vh_[4][4], vl_[4][4];
            const int vrow = f * 16 + vr_lane;
#pragma unroll
            for (int gd = 0; gd < 4; gd++) {
                const uint32_t ro = (uint32_t)(vrow * 128)
                                  + ASWZ(vrow, gd * 32 + vcB);
                ldmat_x4_trans(vh_[gd], base + 4 * ATILE_B + ro);
                ldmat_x4_trans(vl_[gd], base + 5 * ATILE_B + ro);
            }
#pragma unroll
            for (int gd = 0; gd < 4; gd++)
#pragma unroll
                for (int p = 0; p < 2; p++)
                    mma16816(zacc[gd*2+p], ah, vh_[gd][p*2], vh_[gd][p*2+1]);
#pragma unroll
            for (int gd = 0; gd < 4; gd++)
#pragma unroll
                for (int p = 0; p < 2; p++)
                    mma16816(zacc[gd*2+p], ah, vl_[gd][p*2], vl_[gd][p*2+1]);
#pragma unroll
            for (int gd = 0; gd < 4; gd++)
#pragma unroll
                for (int p = 0; p < 2; p++)
                    mma16816(zacc[gd*2+p], al, vh_[gd][p*2], vh_[gd][p*2+1]);
        }
    }

    {
        const int r = q0 + w * 16 + (lane >> 2);
        const int c = (lane & 3) * 2;
#pragma unroll
        for (int nd = 0; nd < 8; nd++) {
            unsigned short h0, l0, h1, l1;
#pragma unroll
            for (int half = 0; half < 2; half++) {
                fsplit(zacc[nd][half * 2 + 0], h0, l0);
                fsplit(zacc[nd][half * 2 + 1], h1, l1);
                const size_t off = bh_off + (size_t)(r + half * 8) * DD + nd * 8 + c;
                *(uint32_t*)(zh + off) = (uint32_t)h1 << 16 | h0;
                *(uint32_t*)(zl + off) = (uint32_t)l1 << 16 | l0;
            }
        }
    }
}

// ---------------------------------------------------------------------------
extern "C" void kernel_launch(void* const* d_in, const int* in_sizes, int n_in,
                              void* d_out, int out_size) {
    const float* x     = (const float*)d_in[0];
    const float* Wq    = (const float*)d_in[1];
    const float* Wk    = (const float*)d_in[2];
    const float* Wq2   = (const float*)d_in[3];
    const float* Wk2   = (const float*)d_in[4];
    const float* Wv    = (const float*)d_in[5];
    const float* Wproj = (const float*)d_in[6];
    float* out = (float*)d_out;

    float2* cs;
    cudaGetSymbolAddress((void**)&cs, g_cs);

    __nv_bfloat16 *xh, *xl, *zh, *zl, *w6h, *w6l;
    cudaGetSymbolAddress((void**)&xh,  g_xh);  cudaGetSymbolAddress((void**)&xl,  g_xl);
    cudaGetSymbolAddress((void**)&zh,  g_zh);  cudaGetSymbolAddress((void**)&zl,  g_zl);
    cudaGetSymbolAddress((void**)&w6h, g_w6h); cudaGetSymbolAddress((void**)&w6l, g_w6l);

    __nv_bfloat16 *qh, *ql, *q2h, *q2l, *kh, *kl, *k2h, *k2l, *vh, *vl;
    cudaGetSymbolAddress((void**)&qh,  g_qh);  cudaGetSymbolAddress((void**)&ql,  g_ql);
    cudaGetSymbolAddress((void**)&q2h, g_q2h); cudaGetSymbolAddress((void**)&q2l, g_q2l);
    cudaGetSymbolAddress((void**)&kh,  g_kh);  cudaGetSymbolAddress((void**)&kl,  g_kl);
    cudaGetSymbolAddress((void**)&k2h, g_k2h); cudaGetSymbolAddress((void**)&k2l, g_k2l);
    cudaGetSymbolAddress((void**)&vh,  g_vh);  cudaGetSymbolAddress((void**)&vl,  g_vl);

    Outs outs;
    outs.hi[0] = qh;  outs.lo[0] = ql;
    outs.hi[1] = kh;  outs.lo[1] = kl;
    outs.hi[2] = q2h; outs.lo[2] = q2l;
    outs.hi[3] = k2h; outs.lo[3] = k2l;
    outs.hi[4] = vh;  outs.lo[4] = vl;

    cudaFuncSetAttribute(gemm_plain,
                         cudaFuncAttributeMaxDynamicSharedMemorySize, GEMM_SMEM);
    cudaFuncSetAttribute(gemm_rope,
                         cudaFuncAttributeMaxDynamicSharedMemorySize, GEMM_SMEM);
    cudaFuncSetAttribute(attn_mma,
                         cudaFuncAttributeMaxDynamicSharedMemorySize, ATTN_SMEM);

    // 0) cos/sin table
    build_cs<<<TT * 32 / 256, 256>>>(cs);

    // 1) split inputs
    split_f32<<<MM * DD / 1024, 256>>>(x, xh, xl);
    split_w6<<<dim3(DD * DD / 1024, 6), 256>>>(Wq, Wk, Wq2, Wk2, Wv, Wproj, w6h, w6l);

    // 2) five fused projections
    gemm_rope<<<dim3(DD / 128, MM / 128, 5), 256, GEMM_SMEM>>>(
        xh, xl, w6h, w6l, outs, cs);

    // 3) attention (3-stage SW128 ring)
    attn_mma<<<dim3(TT / 128, BB * HH), 256, ATTN_SMEM>>>(
        qh, ql, q2h, q2l, kh, kl, k2h, k2l, vh, vl, zh, zl);

    // 4) output projection
    gemm_plain<<<dim3(DD / 128, MM / 128, 1), 256, GEMM_SMEM>>>(
        zh, zl, w6h + (size_t)5 * DD * DD, w6l + (size_t)5 * DD * DD, out);
}

// round 17
// speedup vs baseline: 1.2847x; 1.0198x over previous
#include <cuda_runtime.h>
#include <cuda_bf16.h>
#include <math.h>
#include <stdint.h>

#define BB 2
#define TT 2048
#define DD 1024
#define HH 16
#define DH 64
#define MM (BB*TT)

/* ---- gemm geometry (round 15/16): SW64 64B rows, 3 stages, occ 2 ---- */
#define GTILE_B 8192u
#define GSTAGE_B (4u*GTILE_B)
#define NSTG 3
#define NCH  32
#define GEMM_SMEM (NSTG*GSTAGE_B)   /* 98304 B */
#define FST 132

/* ---- attn geometry (round 16): SW128 128B rows, 3 stages ---- */
#define ATILE_B 8192u
#define ASTAGE_B (6u*ATILE_B)
#define ANSTG 3
#define ATTN_SMEM (ANSTG*ASTAGE_B)  /* 147456 B */
#define QTILE_B 16384u
#define ASWZ(r, cb) ((uint32_t)(cb) ^ (uint32_t)((((r) & 7)) << 4))

// ---------------- scratch (device globals) ----------------------------------
__device__ float2 g_cs[TT*32];
__device__ __nv_bfloat16 g_xh [MM*DD], g_xl [MM*DD];
__device__ __nv_bfloat16 g_zh [MM*DD], g_zl [MM*DD];
__device__ __nv_bfloat16 g_w6h[6*DD*DD], g_w6l[6*DD*DD];
__device__ __nv_bfloat16 g_qh [MM*DD], g_ql [MM*DD];
__device__ __nv_bfloat16 g_q2h[MM*DD], g_q2l[MM*DD];
__device__ __nv_bfloat16 g_kh [MM*DD], g_kl [MM*DD];
__device__ __nv_bfloat16 g_k2h[MM*DD], g_k2l[MM*DD];
__device__ __nv_bfloat16 g_vh [MM*DD], g_vl [MM*DD];

struct Outs { __nv_bfloat16* hi[5]; __nv_bfloat16* lo[5]; };

// ---------------------------------------------------------------------------
__device__ __forceinline__ uint32_t saddr(const void* p) {
    return (uint32_t)__cvta_generic_to_shared(p);
}
__device__ __forceinline__ void ldmat_x4(uint32_t (&r)[4], uint32_t a) {
    asm volatile("ldmatrix.sync.aligned.m8n8.x4.shared.b16 {%0,%1,%2,%3}, [%4];"
                 : "=r"(r[0]), "=r"(r[1]), "=r"(r[2]), "=r"(r[3]) : "r"(a));
}
__device__ __forceinline__ void ldmat_x4_trans(uint32_t (&r)[4], uint32_t a) {
    asm volatile("ldmatrix.sync.aligned.m8n8.x4.trans.shared.b16 {%0,%1,%2,%3}, [%4];"
                 : "=r"(r[0]), "=r"(r[1]), "=r"(r[2]), "=r"(r[3]) : "r"(a));
}
__device__ __forceinline__ void mma16816(float (&d)[4], const uint32_t (&a)[4],
                                         uint32_t b0, uint32_t b1) {
    asm volatile(
        "mma.sync.aligned.m16n8k16.row.col.f32.bf16.bf16.f32 "
        "{%0,%1,%2,%3}, {%4,%5,%6,%7}, {%8,%9}, {%0,%1,%2,%3};"
        : "+f"(d[0]), "+f"(d[1]), "+f"(d[2]), "+f"(d[3])
        : "r"(a[0]), "r"(a[1]), "r"(a[2]), "r"(a[3]), "r"(b0), "r"(b1));
}
__device__ __forceinline__ void cpa16s(uint32_t dst, const void* src) {
    asm volatile("cp.async.cg.shared.global [%0], [%1], 16;"
                 :: "r"(dst), "l"(src));
}
__device__ __forceinline__ void cpa_commit() { asm volatile("cp.async.commit_group;"); }
__device__ __forceinline__ void cpa_wait0()  { asm volatile("cp.async.wait_group 0;"); }
__device__ __forceinline__ void cpa_wait1()  { asm volatile("cp.async.wait_group 1;"); }

// packed split: (a,b) -> hp = {bf16(b)<<16 | bf16(a)}, lp = residuals likewise.
// cvt.rn.bf16x2 uses the same round-to-nearest-even as __float2bfloat16_rn.
__device__ __forceinline__ void fsplit2(float a, float b,
                                        uint32_t& hp, uint32_t& lp) {
    asm("cvt.rn.bf16x2.f32 %0, %1, %2;" : "=r"(hp) : "f"(b), "f"(a));
    const float ha = __uint_as_float(hp << 16);
    const float hb = __uint_as_float(hp & 0xFFFF0000u);
    asm("cvt.rn.bf16x2.f32 %0, %1, %2;" : "=r"(lp) : "f"(b - hb), "f"(a - ha));
}

// ---------------------------------------------------------------------------
// prep: cos/sin table + split x + split 6 weights, one launch
// blocks [0,4096): x | [4096,10240): weights | [10240,10496): cs
// ---------------------------------------------------------------------------
__global__ void prep(const float* __restrict__ x,
                     const float* __restrict__ w0, const float* __restrict__ w1,
                     const float* __restrict__ w2, const float* __restrict__ w3,
                     const float* __restrict__ w4, const float* __restrict__ w5,
                     __nv_bfloat16* __restrict__ xh, __nv_bfloat16* __restrict__ xl,
                     __nv_bfloat16* __restrict__ wh, __nv_bfloat16* __restrict__ wl,
                     float2* __restrict__ cs) {
    const int bid = blockIdx.x;
    if (bid < 4096 + 6144) {
        const float* in;
        __nv_bfloat16 *hi, *lo;
        size_t base;
        if (bid < 4096) {
            in = x; hi = xh; lo = xl;
            base = (size_t)bid * 1024;
        } else {
            const int idx = bid - 4096;
            const int wi  = idx >> 10;
            const float* src[6] = {w0, w1, w2, w3, w4, w5};
            in = src[wi]; hi = wh; lo = wl;
            base = (size_t)wi * DD * DD + (size_t)(idx & 1023) * 1024;
            in -= base - (size_t)(idx & 1023) * 1024;   // in indexed locally below
            in = src[wi];
            // local element base within this weight:
            // handled via explicit offset below
            const size_t loc = (size_t)(idx & 1023) * 1024;
            const size_t i = loc + (size_t)threadIdx.x * 4;
            float4 v = *(const float4*)(in + i);
            uint32_t h0, l0, h1, l1;
            fsplit2(v.x, v.y, h0, l0);
            fsplit2(v.z, v.w, h1, l1);
            *(uint2*)(hi + base - loc + i) = make_uint2(h0, h1);
            *(uint2*)(lo + base - loc + i) = make_uint2(l0, l1);
            return;
        }
        const size_t i = base + (size_t)threadIdx.x * 4;
        float4 v = *(const float4*)(in + i);
        uint32_t h0, l0, h1, l1;
        fsplit2(v.x, v.y, h0, l0);
        fsplit2(v.z, v.w, h1, l1);
        *(uint2*)(hi + i) = make_uint2(h0, h1);
        *(uint2*)(lo + i) = make_uint2(l0, l1);
    } else {
        const int idx = (bid - 10240) * 256 + threadIdx.x;   // < 65536
        const int t = idx >> 5;
        const int i = idx & 31;
        const float inv_freq = powf(10000.0f, -(float)i * (1.0f / 32.0f));
        float c, s;
        sincosf((float)t * inv_freq, &s, &c);
        cs[idx] = make_float2(c, s);
    }
}

// ---------------------------------------------------------------------------
// 3-stage SW64-swizzled gemm mainloop (round 15, unchanged)
// ---------------------------------------------------------------------------
#define GEMM_MAINLOOP(Ah, Al, Wh, Wl, acc, sg, tid, m0, n0, wm, wn, lane)      \
    const uint32_t sb_ = saddr(sg);                                            \
    auto load_chunk = [&](int c) {                                             \
        const uint32_t base = sb_ + (uint32_t)(c % NSTG) * GSTAGE_B;           \
        const int k0 = c * 32;                                                 \
        _Pragma("unroll 2")                                                    \
        for (int i = tid; i < 512; i += 256) {                                 \
            const int r  = i >> 2;                                             \
            const int cb = (i & 3) * 16;                                       \
            const uint32_t sw = (uint32_t)(((r >> 1) & 3) << 4);               \
            const uint32_t so = (uint32_t)(r * 64) + ((uint32_t)cb ^ sw);      \
            const int ck = (i & 3) * 8;                                        \
            cpa16s(base + 0 * GTILE_B + so, Ah + (size_t)(m0 + r) * DD + k0 + ck);\
            cpa16s(base + 1 * GTILE_B + so, Al + (size_t)(m0 + r) * DD + k0 + ck);\
            cpa16s(base + 2 * GTILE_B + so, Wh + (size_t)(n0 + r) * DD + k0 + ck);\
            cpa16s(base + 3 * GTILE_B + so, Wl + (size_t)(n0 + r) * DD + k0 + ck);\
        }                                                                      \
        cpa_commit();                                                          \
    };                                                                         \
    load_chunk(0);                                                             \
    load_chunk(1);                                                             \
    for (int ch = 0; ch < NCH; ch++) {                                         \
        if (ch + 1 < NCH) cpa_wait1();                                         \
        else              cpa_wait0();                                         \
        __syncthreads();                                                       \
        if (ch + 2 < NCH) load_chunk(ch + 2);                                  \
        const uint32_t cur = sb_ + (uint32_t)(ch % NSTG) * GSTAGE_B;           \
        const int ar = wm * 64 + (lane & 15);                                  \
        const uint32_t swA = (uint32_t)(((ar >> 1) & 3) << 4);                 \
        const int br = wn * 32 + ((lane >> 4) & 1) * 8 + (lane & 7);           \
        const uint32_t swB = (uint32_t)(((br >> 1) & 3) << 4);                 \
        _Pragma("unroll")                                                      \
        for (int kk = 0; kk < 2; kk++) {                                       \
            uint32_t ahi[4][4], alo[4][4], bhi[2][4], blo[2][4];               \
            const uint32_t akb = ((uint32_t)(kk * 16 + (lane >> 4) * 8) * 2) ^ swA;\
            _Pragma("unroll")                                                  \
            for (int mi = 0; mi < 4; mi++) {                                   \
                const uint32_t ro = (uint32_t)((ar + mi * 16) * 64) + akb;     \
                ldmat_x4(ahi[mi], cur + 0 * GTILE_B + ro);                     \
                ldmat_x4(alo[mi], cur + 1 * GTILE_B + ro);                     \
            }                                                                  \
            const uint32_t bkb = ((uint32_t)(kk * 16 + ((lane >> 3) & 1) * 8) * 2) ^ swB;\
            _Pragma("unroll")                                                  \
            for (int p = 0; p < 2; p++) {                                      \
                const uint32_t ro = (uint32_t)((br + p * 16) * 64) + bkb;      \
                ldmat_x4(bhi[p], cur + 2 * GTILE_B + ro);                      \
                ldmat_x4(blo[p], cur + 3 * GTILE_B + ro);                      \
            }                                                                  \
            _Pragma("unroll")                                                  \
            for (int mi = 0; mi < 4; mi++)                                     \
                _Pragma("unroll")                                              \
                for (int ni = 0; ni < 4; ni++) {                               \
                    const uint32_t* bh = &bhi[ni >> 1][(ni & 1) * 2];          \
                    mma16816(acc[mi][ni], ahi[mi], bh[0], bh[1]);              \
                }                                                              \
            _Pragma("unroll")                                                  \
            for (int mi = 0; mi < 4; mi++)                                     \
                _Pragma("unroll")                                              \
                for (int ni = 0; ni < 4; ni++) {                               \
                    const uint32_t* bl = &blo[ni >> 1][(ni & 1) * 2];          \
                    mma16816(acc[mi][ni], ahi[mi], bl[0], bl[1]);              \
                }                                                              \
            _Pragma("unroll")                                                  \
            for (int mi = 0; mi < 4; mi++)                                     \
                _Pragma("unroll")                                              \
                for (int ni = 0; ni < 4; ni++) {                               \
                    const uint32_t* bh = &bhi[ni >> 1][(ni & 1) * 2];          \
                    mma16816(acc[mi][ni], alo[mi], bh[0], bh[1]);              \
                }                                                              \
        }                                                                      \
    }

// ---------------------------------------------------------------------------
// out-projection: plain fp32 epilogue
// ---------------------------------------------------------------------------
__global__ void __launch_bounds__(256, 2) gemm_plain(
        const __nv_bfloat16* __restrict__ Ah, const __nv_bfloat16* __restrict__ Al,
        const __nv_bfloat16* __restrict__ Wh, const __nv_bfloat16* __restrict__ Wl,
        float* __restrict__ C) {
    extern __shared__ __nv_bfloat16 sg[];
    const int tid  = threadIdx.x;
    const int wid  = tid >> 5;
    const int lane = tid & 31;
    const int m0 = blockIdx.y * 128;
    const int n0 = blockIdx.x * 128;
    const int wm = wid & 1;
    const int wn = wid >> 1;

    float acc[4][4][4];
#pragma unroll
    for (int i = 0; i < 4; i++)
#pragma unroll
        for (int j = 0; j < 4; j++)
#pragma unroll
            for (int c = 0; c < 4; c++) acc[i][j][c] = 0.0f;

    GEMM_MAINLOOP(Ah, Al, Wh, Wl, acc, sg, tid, m0, n0, wm, wn, lane)

#pragma unroll
    for (int mi = 0; mi < 4; mi++)
#pragma unroll
        for (int ni = 0; ni < 4; ni++) {
            const int r0 = m0 + wm * 64 + mi * 16 + (lane >> 2);
            const int c0 = n0 + wn * 32 + ni * 8 + (lane & 3) * 2;
            *(float2*)(C + (size_t)r0 * 1024 + c0) =
                make_float2(acc[mi][ni][0], acc[mi][ni][1]);
            *(float2*)(C + (size_t)(r0 + 8) * 1024 + c0) =
                make_float2(acc[mi][ni][2], acc[mi][ni][3]);
        }
}

// ---------------------------------------------------------------------------
// projections: fused vectorized RoPE + hi/lo split epilogue.
// q (zi=0) and q2 (zi=2) are pre-scaled by 1/64 (exact power-of-2) so the
// attention kernel needs no 1/Dh^2 scaling.
// ---------------------------------------------------------------------------
__global__ void __launch_bounds__(256, 2) gemm_rope(
        const __nv_bfloat16* __restrict__ Ah, const __nv_bfloat16* __restrict__ Al,
        const __nv_bfloat16* __restrict__ Wh, const __nv_bfloat16* __restrict__ Wl,
        Outs outs, const float2* __restrict__ cs) {
    extern __shared__ __nv_bfloat16 sg[];
    const int zi = blockIdx.z;
    Wh += (size_t)zi * DD * DD;
    Wl += (size_t)zi * DD * DD;

    const int tid  = threadIdx.x;
    const int wid  = tid >> 5;
    const int lane = tid & 31;
    const int m0 = blockIdx.y * 128;
    const int n0 = blockIdx.x * 128;
    const int wm = wid & 1;
    const int wn = wid >> 1;

    float acc[4][4][4];
#pragma unroll
    for (int i = 0; i < 4; i++)
#pragma unroll
        for (int j = 0; j < 4; j++)
#pragma unroll
            for (int c = 0; c < 4; c++) acc[i][j][c] = 0.0f;

    GEMM_MAINLOOP(Ah, Al, Wh, Wl, acc, sg, tid, m0, n0, wm, wn, lane)

    float* Sf = (float*)sg;
    __syncthreads();
#pragma unroll
    for (int mi = 0; mi < 4; mi++)
#pragma unroll
        for (int ni = 0; ni < 4; ni++) {
            const int rl = wm * 64 + mi * 16 + (lane >> 2);
            const int c0 = wn * 32 + ni * 8 + (lane & 3) * 2;
            *(float2*)(Sf + rl * FST + c0) =
                make_float2(acc[mi][ni][0], acc[mi][ni][1]);
            *(float2*)(Sf + (rl + 8) * FST + c0) =
                make_float2(acc[mi][ni][2], acc[mi][ni][3]);
        }
    __syncthreads();

    __nv_bfloat16* Oh = outs.hi[zi];
    __nv_bfloat16* Ol = outs.lo[zi];
    const bool dorope = (zi != 4);
    const float sc = (zi == 0 || zi == 2) ? 0.015625f : 1.0f;  // 1/64 exact
    for (int it = tid; it < 2048; it += 256) {
        const int r  = it >> 4;
        const int c8 = (it & 15) * 8;
        float xt[8];
        *(float4*)(xt)     = *(const float4*)(Sf + r * FST + c8);
        *(float4*)(xt + 4) = *(const float4*)(Sf + r * FST + c8 + 4);
        float y[8];
        if (dorope) {
            const bool first = (c8 & 32) == 0;
            const int po = first ? 32 : -32;
            float xp[8];
            *(float4*)(xp)     = *(const float4*)(Sf + r * FST + c8 + po);
            *(float4*)(xp + 4) = *(const float4*)(Sf + r * FST + c8 + po + 4);
            const int t  = (m0 + r) & (TT - 1);
            const int ib = c8 & 31;
#pragma unroll
            for (int j = 0; j < 8; j++) {
                const float2 cc = cs[t * 32 + ib + j];
                y[j] = first ? fmaf(xt[j], cc.x, xp[j] * cc.y)
                             : fmaf(-xp[j], cc.y, xt[j] * cc.x);
            }
        } else {
#pragma unroll
            for (int j = 0; j < 8; j++) y[j] = xt[j];
        }
#pragma unroll
        for (int j = 0; j < 8; j++) y[j] *= sc;
        uint4 hv, lv;
        fsplit2(y[0], y[1], hv.x, lv.x);
        fsplit2(y[2], y[3], hv.y, lv.y);
        fsplit2(y[4], y[5], hv.z, lv.z);
        fsplit2(y[6], y[7], hv.w, lv.w);
        const size_t go = (size_t)(m0 + r) * DD + n0 + c8;
        *(uint4*)(Oh + go) = hv;
        *(uint4*)(Ol + go) = lv;
    }
}

// ---------------------------------------------------------------------------
// Tensor-core causal bilinear attention (round-16 pipeline, slimmer P-chain)
// ---------------------------------------------------------------------------
__global__ void __launch_bounds__(256, 1) attn_mma(
        const __nv_bfloat16* __restrict__ qh,  const __nv_bfloat16* __restrict__ ql,
        const __nv_bfloat16* __restrict__ q2h, const __nv_bfloat16* __restrict__ q2l,
        const __nv_bfloat16* __restrict__ kh,  const __nv_bfloat16* __restrict__ kl,
        const __nv_bfloat16* __restrict__ k2h, const __nv_bfloat16* __restrict__ k2l,
        const __nv_bfloat16* __restrict__ vh,  const __nv_bfloat16* __restrict__ vl,
        __nv_bfloat16* __restrict__ zh, __nv_bfloat16* __restrict__ zl) {
    extern __shared__ __nv_bfloat16 sb2[];
    const uint32_t ab = saddr(sb2);
    const int tid  = threadIdx.x;
    const int lane = tid & 31;
    const int w    = tid >> 5;
    const int qb = (int)gridDim.x - 1 - (int)blockIdx.x;
    const int q0 = qb * 128;
    const int b  = blockIdx.y >> 4;
    const int h  = blockIdx.y & 15;
    const size_t bh_off = (size_t)b * TT * DD + h * DH;

    {
        const __nv_bfloat16* src[4] = {qh, ql, q2h, q2l};
#pragma unroll
        for (int a = 0; a < 4; a++) {
            for (int i = tid; i < 1024; i += 256) {
                const int r = i >> 3;
                const uint32_t cb = (uint32_t)(i & 7) * 16;
                cpa16s(ab + a * QTILE_B + (uint32_t)(r * 128) + ASWZ(r, cb),
                       src[a] + bh_off + (size_t)(q0 + r) * DD + (i & 7) * 8);
            }
        }
        cpa_commit();
        cpa_wait0();
        __syncthreads();
    }

    uint32_t fqh[4][4], fql[4][4], fq2h[4][4], fq2l[4][4];
    {
        const int ar = w * 16 + (lane & 15);
        const uint32_t akb = (uint32_t)(lane >> 4) * 16;
#pragma unroll
        for (int kf = 0; kf < 4; kf++) {
            const uint32_t ro = (uint32_t)(ar * 128) + ASWZ(ar, kf * 32 + akb);
            ldmat_x4(fqh [kf], ab + 0 * QTILE_B + ro);
            ldmat_x4(fql [kf], ab + 1 * QTILE_B + ro);
            ldmat_x4(fq2h[kf], ab + 2 * QTILE_B + ro);
            ldmat_x4(fq2l[kf], ab + 3 * QTILE_B + ro);
        }
    }
    __syncthreads();

    float zacc[8][4];
#pragma unroll
    for (int i = 0; i < 8; i++)
#pragma unroll
        for (int j = 0; j < 4; j++) zacc[i][j] = 0.0f;

    const int nkv = 2 * qb + 2;
    const int br = (lane & 7) + ((lane >> 4) & 1) * 8;
    const uint32_t bkB = (uint32_t)((lane >> 3) & 1) * 16;

    auto load_tile = [&](int kj) {
        const uint32_t base = ab + (uint32_t)(kj % ANSTG) * ASTAGE_B;
        const int kv0 = kj * 64;
        const __nv_bfloat16* src[6] = {kh, kl, k2h, k2l, vh, vl};
#pragma unroll
        for (int a = 0; a < 6; a++) {
            for (int i = tid; i < 512; i += 256) {
                const int r = i >> 3;
                const uint32_t cb = (uint32_t)(i & 7) * 16;
                cpa16s(base + a * ATILE_B + (uint32_t)(r * 128) + ASWZ(r, cb),
                       src[a] + bh_off + (size_t)(kv0 + r) * DD + (i & 7) * 8);
            }
        }
        cpa_commit();
    };

    load_tile(0);
    load_tile(1);

    for (int kj = 0; kj < nkv; kj++) {
        if (kj + 1 < nkv) cpa_wait1();
        else              cpa_wait0();
        __syncthreads();
        if (kj + 2 < nkv) load_tile(kj + 2);

        const uint32_t base = ab + (uint32_t)(kj % ANSTG) * ASTAGE_B;
        const int kv0 = kj * 64;
        const bool masked = (kv0 >= q0);

        uint32_t ph[8][2], pl[8][2];
#pragma unroll
        for (int g = 0; g < 4; g++) {
            float s1f[2][4], s2f[2][4];
#pragma unroll
            for (int p = 0; p < 2; p++)
#pragma unroll
                for (int e = 0; e < 4; e++) { s1f[p][e] = 0.0f; s2f[p][e] = 0.0f; }

            const int krow = g * 16 + br;
#pragma unroll
            for (int kf = 0; kf < 4; kf++) {
                uint32_t kh_[4], kl_[4], k2h_[4], k2l_[4];
                const uint32_t ro = (uint32_t)(krow * 128)
                                  + ASWZ(krow, kf * 32 + bkB);
                ldmat_x4(kh_,  base + 0 * ATILE_B + ro);
                ldmat_x4(kl_,  base + 1 * ATILE_B + ro);
                ldmat_x4(k2h_, base + 2 * ATILE_B + ro);
                ldmat_x4(k2l_, base + 3 * ATILE_B + ro);
#pragma unroll
                for (int p = 0; p < 2; p++) {
                    mma16816(s1f[p], fqh[kf],  kh_[p*2],  kh_[p*2+1]);
                    mma16816(s2f[p], fq2h[kf], k2h_[p*2], k2h_[p*2+1]);
                }
#pragma unroll
                for (int p = 0; p < 2; p++) {
                    mma16816(s1f[p], fqh[kf],  kl_[p*2],  kl_[p*2+1]);
                    mma16816(s2f[p], fq2h[kf], k2l_[p*2], k2l_[p*2+1]);
                }
#pragma unroll
                for (int p = 0; p < 2; p++) {
                    mma16816(s1f[p], fql[kf],  kh_[p*2],  kh_[p*2+1]);
                    mma16816(s2f[p], fq2l[kf], k2h_[p*2], k2h_[p*2+1]);
                }
            }
#pragma unroll
            for (int p = 0; p < 2; p++) {
                const int j = g * 2 + p;
                float pr[4];
#pragma unroll
                for (int e = 0; e < 4; e++) pr[e] = s1f[p][e] * s2f[p][e];
                if (masked) {
                    const int qr = q0 + w * 16 + (lane >> 2);
                    const int kc = kv0 + j * 8 + (lane & 3) * 2;
                    if (kc     > qr)     pr[0] = 0.0f;
                    if (kc + 1 > qr)     pr[1] = 0.0f;
                    if (kc     > qr + 8) pr[2] = 0.0f;
                    if (kc + 1 > qr + 8) pr[3] = 0.0f;
                }
                fsplit2(pr[0], pr[1], ph[j][0], pl[j][0]);
                fsplit2(pr[2], pr[3], ph[j][1], pl[j][1]);
            }
        }

        const int vr_lane = ((lane >> 3) & 1) * 8 + (lane & 7);
        const uint32_t vcB = (uint32_t)((lane >> 4) & 1) * 16;
#pragma unroll
        for (int f = 0; f < 4; f++) {
            uint32_t ah[4] = {ph[2*f][0], ph[2*f][1], ph[2*f+1][0], ph[2*f+1][1]};
            uint32_t al[4] = {pl[2*f][0], pl[2*f][1], pl[2*f+1][0], pl[2*f+1][1]};
            uint32_t vh_[4][4], vl_[4][4];
            const int vrow = f * 16 + vr_lane;
#pragma unroll
            for (int gd = 0; gd < 4; gd++) {
                const uint32_t ro = (uint32_t)(vrow * 128)
                                  + ASWZ(vrow, gd * 32 + vcB);
                ldmat_x4_trans(vh_[gd], base + 4 * ATILE_B + ro);
                ldmat_x4_trans(vl_[gd], base + 5 * ATILE_B + ro);
            }
#pragma unroll
            for (int gd = 0; gd < 4; gd++)
#pragma unroll
                for (int p = 0; p < 2; p++)
                    mma16816(zacc[gd*2+p], ah, vh_[gd][p*2], vh_[gd][p*2+1]);
#pragma unroll
            for (int gd = 0; gd < 4; gd++)
#pragma unroll
                for (int p = 0; p < 2; p++)
                    mma16816(zacc[gd*2+p], ah, vl_[gd][p*2], vl_[gd][p*2+1]);
#pragma unroll
            for (int gd = 0; gd < 4; gd++)
#pragma unroll
                for (int p = 0; p < 2; p++)
                    mma16816(zacc[gd*2+p], al, vh_[gd][p*2], vh_[gd][p*2+1]);
        }
    }

    {
        const int r = q0 + w * 16 + (lane >> 2);
        const int c = (lane & 3) * 2;
#pragma unroll
        for (int nd = 0; nd < 8; nd++) {
#pragma unroll
            for (int half = 0; half < 2; half++) {
                uint32_t hp, lp;
                fsplit2(zacc[nd][half * 2 + 0], zacc[nd][half * 2 + 1], hp, lp);
                const size_t off = bh_off + (size_t)(r + half * 8) * DD + nd * 8 + c;
                *(uint32_t*)(zh + off) = hp;
                *(uint32_t*)(zl + off) = lp;
            }
        }
    }
}

// ---------------------------------------------------------------------------
extern "C" void kernel_launch(void* const* d_in, const int* in_sizes, int n_in,
                              void* d_out, int out_size) {
    const float* x     = (const float*)d_in[0];
    const float* Wq    = (const float*)d_in[1];
    const float* Wk    = (const float*)d_in[2];
    const float* Wq2   = (const float*)d_in[3];
    const float* Wk2   = (const float*)d_in[4];
    const float* Wv    = (const float*)d_in[5];
    const float* Wproj = (const float*)d_in[6];
    float* out = (float*)d_out;

    float2* cs;
    cudaGetSymbolAddress((void**)&cs, g_cs);

    __nv_bfloat16 *xh, *xl, *zh, *zl, *w6h, *w6l;
    cudaGetSymbolAddress((void**)&xh,  g_xh);  cudaGetSymbolAddress((void**)&xl,  g_xl);
    cudaGetSymbolAddress((void**)&zh,  g_zh);  cudaGetSymbolAddress((void**)&zl,  g_zl);
    cudaGetSymbolAddress((void**)&w6h, g_w6h); cudaGetSymbolAddress((void**)&w6l, g_w6l);

    __nv_bfloat16 *qh, *ql, *q2h, *q2l, *kh, *kl, *k2h, *k2l, *vh, *vl;
    cudaGetSymbolAddress((void**)&qh,  g_qh);  cudaGetSymbolAddress((void**)&ql,  g_ql);
    cudaGetSymbolAddress((void**)&q2h, g_q2h); cudaGetSymbolAddress((void**)&q2l, g_q2l);
    cudaGetSymbolAddress((void**)&kh,  g_kh);  cudaGetSymbolAddress((void**)&kl,  g_kl);
    cudaGetSymbolAddress((void**)&k2h, g_k2h); cudaGetSymbolAddress((void**)&k2l, g_k2l);
    cudaGetSymbolAddress((void**)&vh,  g_vh);  cudaGetSymbolAddress((void**)&vl,  g_vl);

    Outs outs;
    outs.hi[0] = qh;  outs.lo[0] = ql;
    outs.hi[1] = kh;  outs.lo[1] = kl;
    outs.hi[2] = q2h; outs.lo[2] = q2l;
    outs.hi[3] = k2h; outs.lo[3] = k2l;
    outs.hi[4] = vh;  outs.lo[4] = vl;

    cudaFuncSetAttribute(gemm_plain,
                         cudaFuncAttributeMaxDynamicSharedMemorySize, GEMM_SMEM);
    cudaFuncSetAttribute(gemm_rope,
                         cudaFuncAttributeMaxDynamicSharedMemorySize, GEMM_SMEM);
    cudaFuncSetAttribute(attn_mma,
                         cudaFuncAttributeMaxDynamicSharedMemorySize, ATTN_SMEM);

    // 0) combined table + splits
    prep<<<10496, 256>>>(x, Wq, Wk, Wq2, Wk2, Wv, Wproj, xh, xl, w6h, w6l, cs);

    // 1) five fused projections (q/q2 pre-scaled by 1/64)
    gemm_rope<<<dim3(DD / 128, MM / 128, 5), 256, GEMM_SMEM>>>(
        xh, xl, w6h, w6l, outs, cs);

    // 2) attention
    attn_mma<<<dim3(TT / 128, BB * HH), 256, ATTN_SMEM>>>(
        qh, ql, q2h, q2l, kh, kl, k2h, k2l, vh, vl, zh, zl);

    // 3) output projection
    gemm_plain<<<dim3(DD / 128, MM / 128, 1), 256, GEMM_SMEM>>>(
        zh, zl, w6h + (size_t)5 * DD * DD, w6l + (size_t)5 * DD * DD, out);
}